// round 10
// baseline (speedup 1.0000x reference)
#include <cuda_runtime.h>
#include <cuda_bf16.h>
#include <cstdint>
#include <math.h>

// ---------------------------------------------------------------------------
// Problem constants
// ---------------------------------------------------------------------------
constexpr int B = 4;
constexpr int S = 2048;
constexpr int E = 1024;
constexpr int M_ROWS = B * S;   // 8192

// GEMM tiling: CTA 128x128 (4 warps of 64x64), KB=64 bf16 per chunk
constexpr int TM = 128, TN = 128, KB = 64;
constexpr int NTHR = 128;
constexpr int TILE_BYTES = 128 * 128;          // 16KB per operand tile
constexpr int STAGE_BYTES = 4 * TILE_BYTES;    // Ah, Al, Bh, Bl = 64KB
constexpr int NSTAGE = 3;
constexpr int SMEM_SZ = NSTAGE * STAGE_BYTES;  // 192KB
constexpr int EPIT = 132;                      // fp32 epilogue pitch (words)

// ---------------------------------------------------------------------------
// Scratch (device globals — no allocations allowed)
// ---------------------------------------------------------------------------
__device__ __nv_bfloat16 g_qh[(size_t)M_ROWS * E], g_ql[(size_t)M_ROWS * E];
__device__ __nv_bfloat16 g_kh[(size_t)M_ROWS * E], g_kl[(size_t)M_ROWS * E];
__device__ __nv_bfloat16 g_vh[(size_t)M_ROWS * E], g_vl[(size_t)M_ROWS * E];
__device__ __nv_bfloat16 g_wqh[(size_t)E * E], g_wql[(size_t)E * E];
__device__ __nv_bfloat16 g_wkh[(size_t)E * E], g_wkl[(size_t)E * E];
__device__ __nv_bfloat16 g_wvh[(size_t)E * E], g_wvl[(size_t)E * E];
__device__ __nv_bfloat16 g_woh[(size_t)E * E], g_wol[(size_t)E * E];
__device__ __nv_bfloat16 g_Qh[(size_t)M_ROWS * E], g_Ql[(size_t)M_ROWS * E];
__device__ __nv_bfloat16 g_Kh[(size_t)M_ROWS * E], g_Kl[(size_t)M_ROWS * E];
__device__ __nv_bfloat16 g_Vth[(size_t)B * E * S], g_Vtl[(size_t)B * E * S];
__device__ float         g_Sc[(size_t)B * S * S];
__device__ __nv_bfloat16 g_Ph[(size_t)B * S * S], g_Pl[(size_t)B * S * S];
__device__ __nv_bfloat16 g_AOh[(size_t)M_ROWS * E], g_AOl[(size_t)M_ROWS * E];

// ---------------------------------------------------------------------------
// PTX helpers (Ampere-compatible only: cp.async, ldmatrix, mma.sync)
// ---------------------------------------------------------------------------
__device__ __forceinline__ uint32_t smem_u32(const void* p) {
    uint32_t a;
    asm("{ .reg .u64 t; cvta.to.shared.u64 t, %1; cvt.u32.u64 %0, t; }" : "=r"(a) : "l"(p));
    return a;
}
#define SWZ(o) ((uint32_t)(o) ^ ((((uint32_t)(o)) >> 3) & 0x70))

#define CP_ASYNC16(dst, src) \
    asm volatile("cp.async.cg.shared.global [%0], [%1], 16;" :: "r"(dst), "l"(src) : "memory")
#define CP_COMMIT() asm volatile("cp.async.commit_group;" ::: "memory")
#define CP_WAIT0()  asm volatile("cp.async.wait_group 0;" ::: "memory")
#define CP_WAIT1()  asm volatile("cp.async.wait_group 1;" ::: "memory")

#define LDSM4(r0, r1, r2, r3, a) \
    asm volatile("ldmatrix.sync.aligned.m8n8.x4.shared.b16 {%0,%1,%2,%3}, [%4];" \
                 : "=r"(r0), "=r"(r1), "=r"(r2), "=r"(r3) : "r"(a))

#define MMA16816(c, a, b0, b1) \
    asm volatile("mma.sync.aligned.m16n8k16.row.col.f32.bf16.bf16.f32 " \
                 "{%0,%1,%2,%3},{%4,%5,%6,%7},{%8,%9},{%0,%1,%2,%3};" \
                 : "+f"((c)[0]), "+f"((c)[1]), "+f"((c)[2]), "+f"((c)[3]) \
                 : "r"((a)[0]), "r"((a)[1]), "r"((a)[2]), "r"((a)[3]), \
                   "r"(b0), "r"(b1))

// ---------------------------------------------------------------------------
// Batched fp32 -> (bf16 hi, bf16 lo) conversions (blockIdx.y selects tensor)
// ---------------------------------------------------------------------------
__device__ __forceinline__ void cvt_body(const float* __restrict__ in,
                                         __nv_bfloat16* __restrict__ h,
                                         __nv_bfloat16* __restrict__ l)
{
    int i = (blockIdx.x * 256 + threadIdx.x) * 8;
    float4 a = *(const float4*)(in + i);
    float4 b2 = *(const float4*)(in + i + 4);
    float v[8] = {a.x, a.y, a.z, a.w, b2.x, b2.y, b2.z, b2.w};
    unsigned short hb[8], lb[8];
    #pragma unroll
    for (int j = 0; j < 8; j++) {
        __nv_bfloat16 hv = __float2bfloat16(v[j]);
        float lo = v[j] - __bfloat162float(hv);
        __nv_bfloat16 lv = __float2bfloat16(lo);
        hb[j] = *(unsigned short*)&hv;
        lb[j] = *(unsigned short*)&lv;
    }
    *(uint4*)(h + i) = *(uint4*)hb;
    *(uint4*)(l + i) = *(uint4*)lb;
}

__global__ __launch_bounds__(256) void cvt3(
    const float* __restrict__ i0, const float* __restrict__ i1, const float* __restrict__ i2,
    __nv_bfloat16* h0, __nv_bfloat16* l0, __nv_bfloat16* h1, __nv_bfloat16* l1,
    __nv_bfloat16* h2, __nv_bfloat16* l2)
{
    const int z = blockIdx.y;
    const float* in = (z == 0) ? i0 : (z == 1) ? i1 : i2;
    __nv_bfloat16* h = (z == 0) ? h0 : (z == 1) ? h1 : h2;
    __nv_bfloat16* l = (z == 0) ? l0 : (z == 1) ? l1 : l2;
    cvt_body(in, h, l);
}

__global__ __launch_bounds__(256) void cvt4(
    const float* __restrict__ i0, const float* __restrict__ i1,
    const float* __restrict__ i2, const float* __restrict__ i3,
    __nv_bfloat16* h0, __nv_bfloat16* l0, __nv_bfloat16* h1, __nv_bfloat16* l1,
    __nv_bfloat16* h2, __nv_bfloat16* l2, __nv_bfloat16* h3, __nv_bfloat16* l3)
{
    const int z = blockIdx.y;
    const float* in = (z == 0) ? i0 : (z == 1) ? i1 : (z == 2) ? i2 : i3;
    __nv_bfloat16* h = (z == 0) ? h0 : (z == 1) ? h1 : (z == 2) ? h2 : h3;
    __nv_bfloat16* l = (z == 0) ? l0 : (z == 1) ? l1 : (z == 2) ? l2 : l3;
    cvt_body(in, h, l);
}

// ---------------------------------------------------------------------------
// Fused causal softmax: fp32 scores -> bf16-pair probabilities (zeros padded
// to the 128-multiple so attn@V can run dense up to the diagonal tile).
// ---------------------------------------------------------------------------
__global__ __launch_bounds__(256) void softmax_pair(const float* __restrict__ Sc,
                                                    __nv_bfloat16* __restrict__ Ph,
                                                    __nv_bfloat16* __restrict__ Pl)
{
    const int row = blockIdx.x;
    const int b = row >> 11, q = row & (S - 1);
    const float* ptr = Sc + (size_t)b * S * S + (size_t)q * S;
    const int len = q + 1;
    const int plen = ((q >> 7) + 1) << 7;
    const int tid = threadIdx.x;

    float vals[8];
    float m = -INFINITY;
    #pragma unroll
    for (int i = 0; i < 8; i++) {
        int k = tid + i * 256;
        vals[i] = (k < len) ? ptr[k] : -INFINITY;
        m = fmaxf(m, vals[i]);
    }
    __shared__ float red[256];
    red[tid] = m;
    __syncthreads();
    for (int s = 128; s > 0; s >>= 1) {
        if (tid < s) red[tid] = fmaxf(red[tid], red[tid + s]);
        __syncthreads();
    }
    m = red[0];
    __syncthreads();
    float sum = 0.f;
    #pragma unroll
    for (int i = 0; i < 8; i++) {
        int k = tid + i * 256;
        vals[i] = (k < len) ? __expf(vals[i] - m) : 0.f;
        sum += vals[i];
    }
    red[tid] = sum;
    __syncthreads();
    for (int s = 128; s > 0; s >>= 1) {
        if (tid < s) red[tid] += red[tid + s];
        __syncthreads();
    }
    const float inv = 1.0f / red[0];

    __nv_bfloat16* ph = Ph + (size_t)b * S * S + (size_t)q * S;
    __nv_bfloat16* pl = Pl + (size_t)b * S * S + (size_t)q * S;
    #pragma unroll
    for (int i = 0; i < 8; i++) {
        int k = tid + i * 256;
        if (k < plen) {
            float p = vals[i] * inv;
            __nv_bfloat16 h = __float2bfloat16(p);
            ph[k] = h;
            pl[k] = __float2bfloat16(p - __bfloat162float(h));
        }
    }
}

// ---------------------------------------------------------------------------
// GEMM core: 128x128 fp32 tile of A[M,K]*Bop[N,K]^T (split-bf16, 3 terms),
// result left in smem ep[128][EPIT].
// 4 warps of 64x64, m16n8k16 via ldmatrix, 3-stage cp.async pipeline.
// Term-major MMA ordering spaces dependent MMAs 8 apart for ILP.
// ---------------------------------------------------------------------------
__device__ __forceinline__ void gemm_core(
    const __nv_bfloat16* __restrict__ Ah, const __nv_bfloat16* __restrict__ Al,
    const __nv_bfloat16* __restrict__ Bh, const __nv_bfloat16* __restrict__ Bl,
    int m0, int n0, int lda, int ldb, int NC, char* smem)
{
    const uint32_t smb = smem_u32(smem);
    const int tid = threadIdx.x;
    const int wid = tid >> 5, lane = tid & 31;
    const int warp_m = wid >> 1;        // 0..1 -> 64-row half
    const int warp_n = wid & 1;         // 0..1 -> 64-col half

    auto load_chunk = [&](int c, int s) {
        const int k0 = c * KB;
        const uint32_t stage = smb + s * STAGE_BYTES;
        const __nv_bfloat16* gp[4] = {Ah, Al, Bh, Bl};
        #pragma unroll
        for (int t = 0; t < 4; t++) {
            const __nv_bfloat16* g = gp[t];
            const int r0 = (t < 2) ? m0 : n0;
            const int ld = (t < 2) ? lda : ldb;
            const uint32_t tbase = stage + t * TILE_BYTES;
            #pragma unroll
            for (int i = 0; i < 8; i++) {
                int sg = tid + NTHR * i;
                int r = sg >> 3, sc = sg & 7;
                CP_ASYNC16(tbase + SWZ(r * 128 + sc * 16),
                           g + (size_t)(r0 + r) * ld + k0 + sc * 8);
            }
        }
        CP_COMMIT();
    };

    float acc[4][8][4] = {};

    load_chunk(0, 0);
    if (NC > 1) load_chunk(1, 1);

    const int lg = lane >> 3, lr = lane & 7;
    const int rowA = warp_m * 64 + lr + (lg & 1) * 8;
    const int kA   = (lg >> 1) * 16;
    const int rowB = warp_n * 64 + lr + (lg >> 1) * 8;
    const int kBo  = (lg & 1) * 16;

    for (int c = 0; c < NC; c++) {
        if (c == NC - 1) { CP_WAIT0(); } else { CP_WAIT1(); }
        __syncthreads();
        if (c + 2 < NC) load_chunk(c + 2, (c + 2) % NSTAGE);

        const uint32_t stage = smb + (c % NSTAGE) * STAGE_BYTES;
        const uint32_t aH = stage, aL = stage + TILE_BYTES;
        const uint32_t bH = stage + 2 * TILE_BYTES, bL = stage + 3 * TILE_BYTES;

        #pragma unroll
        for (int ks = 0; ks < 4; ks++) {
            const int koA = ks * 32 + kA;
            const int koB = ks * 32 + kBo;
            uint32_t bh[4][4], bl[4][4];
            #pragma unroll
            for (int jp = 0; jp < 4; jp++) {
                uint32_t off = SWZ((rowB + jp * 16) * 128 + koB);
                LDSM4(bh[jp][0], bh[jp][1], bh[jp][2], bh[jp][3], bH + off);
                LDSM4(bl[jp][0], bl[jp][1], bl[jp][2], bl[jp][3], bL + off);
            }
            #pragma unroll
            for (int i = 0; i < 4; i++) {
                uint32_t ah[4], al[4];
                uint32_t off = SWZ((rowA + i * 16) * 128 + koA);
                LDSM4(ah[0], ah[1], ah[2], ah[3], aH + off);
                LDSM4(al[0], al[1], al[2], al[3], aL + off);
                // term-major: 8 independent MMAs between touches of same acc
                #pragma unroll
                for (int jp = 0; jp < 4; jp++) {
                    MMA16816(acc[i][2 * jp],     ah, bh[jp][0], bh[jp][1]);
                    MMA16816(acc[i][2 * jp + 1], ah, bh[jp][2], bh[jp][3]);
                }
                #pragma unroll
                for (int jp = 0; jp < 4; jp++) {
                    MMA16816(acc[i][2 * jp],     al, bh[jp][0], bh[jp][1]);
                    MMA16816(acc[i][2 * jp + 1], al, bh[jp][2], bh[jp][3]);
                }
                #pragma unroll
                for (int jp = 0; jp < 4; jp++) {
                    MMA16816(acc[i][2 * jp],     ah, bl[jp][0], bl[jp][1]);
                    MMA16816(acc[i][2 * jp + 1], ah, bl[jp][2], bl[jp][3]);
                }
            }
        }
        __syncthreads();
    }

    // regs -> smem ep
    float* ep = (float*)smem;
    const int erow = lane >> 2;
    const int ecol = (lane & 3) * 2;
    #pragma unroll
    for (int i = 0; i < 4; i++) {
        int rbase = warp_m * 64 + i * 16 + erow;
        #pragma unroll
        for (int j = 0; j < 8; j++) {
            int cc = warp_n * 64 + j * 8 + ecol;
            ep[rbase * EPIT + cc]           = acc[i][j][0];
            ep[rbase * EPIT + cc + 1]       = acc[i][j][1];
            ep[(rbase + 8) * EPIT + cc]     = acc[i][j][2];
            ep[(rbase + 8) * EPIT + cc + 1] = acc[i][j][3];
        }
    }
    __syncthreads();
}

// bf16-pair store helper: ep[128][EPIT] (+bias)*scale -> row-major pair arrays
__device__ __forceinline__ void store_pair(
    const float* ep, const float* bias, float scale,
    __nv_bfloat16* oH, __nv_bfloat16* oL, int m0, int n0, int ldc)
{
    const int tid = threadIdx.x;
    #pragma unroll
    for (int i = 0; i < 16; i++) {
        int idx = tid + NTHR * i;
        int r = idx >> 4, c8 = (idx & 15) * 8;
        unsigned short hb[8], lb[8];
        #pragma unroll
        for (int j = 0; j < 8; j++) {
            float v = ep[r * EPIT + c8 + j];
            if (bias) v = (v + bias[n0 + c8 + j]) * scale;
            __nv_bfloat16 hv = __float2bfloat16(v);
            float lo = v - __bfloat162float(hv);
            __nv_bfloat16 lv = __float2bfloat16(lo);
            hb[j] = *(unsigned short*)&hv;
            lb[j] = *(unsigned short*)&lv;
        }
        size_t off = (size_t)(m0 + r) * ldc + n0 + c8;
        *(uint4*)(oH + off) = *(uint4*)hb;
        *(uint4*)(oL + off) = *(uint4*)lb;
    }
}

// ---------------------------------------------------------------------------
// Fused Q/K/V projection: blockIdx.z selects tensor. Q folds the 1/32 scale;
// V writes directly in transposed [b][e][s] bf16-pair layout.
// ---------------------------------------------------------------------------
__global__ __launch_bounds__(NTHR, 1) void proj_qkv(
    const __nv_bfloat16* __restrict__ qh, const __nv_bfloat16* __restrict__ ql,
    const __nv_bfloat16* __restrict__ kh, const __nv_bfloat16* __restrict__ kl,
    const __nv_bfloat16* __restrict__ vh, const __nv_bfloat16* __restrict__ vl,
    const __nv_bfloat16* __restrict__ wqh, const __nv_bfloat16* __restrict__ wql,
    const __nv_bfloat16* __restrict__ wkh, const __nv_bfloat16* __restrict__ wkl,
    const __nv_bfloat16* __restrict__ wvh, const __nv_bfloat16* __restrict__ wvl,
    const float* __restrict__ bq, const float* __restrict__ bk, const float* __restrict__ bv,
    __nv_bfloat16* Qh, __nv_bfloat16* Ql, __nv_bfloat16* Kh, __nv_bfloat16* Kl,
    __nv_bfloat16* Vth, __nv_bfloat16* Vtl)
{
    extern __shared__ __align__(1024) char smem[];
    const int z = blockIdx.z;
    const int m0 = blockIdx.y * TM, n0 = blockIdx.x * TN;

    const __nv_bfloat16 *Ah, *Al, *Bh, *Bl;
    const float* bias;
    if (z == 0)      { Ah = qh; Al = ql; Bh = wqh; Bl = wql; bias = bq; }
    else if (z == 1) { Ah = kh; Al = kl; Bh = wkh; Bl = wkl; bias = bk; }
    else             { Ah = vh; Al = vl; Bh = wvh; Bl = wvl; bias = bv; }

    gemm_core(Ah, Al, Bh, Bl, m0, n0, E, E, E / KB, smem);
    const float* ep = (const float*)smem;
    const int tid = threadIdx.x;

    if (z == 0) {
        store_pair(ep, bias, 0.03125f, Qh, Ql, m0, n0, E);
    } else if (z == 1) {
        store_pair(ep, bias, 1.0f, Kh, Kl, m0, n0, E);
    } else {
        // transposed store: V[m0+r][n0+col] -> Vt[b][n0+col][s0+r]
        const int bb = m0 >> 11;
        const int s0 = m0 & (S - 1);
        const int col = tid;              // 0..127
        const float bcol = bias[n0 + col];
        __nv_bfloat16* oH = Vth + ((size_t)bb * E + n0 + col) * S + s0;
        __nv_bfloat16* oL = Vtl + ((size_t)bb * E + n0 + col) * S + s0;
        #pragma unroll
        for (int r0 = 0; r0 < 128; r0 += 8) {
            unsigned short hb[8], lb[8];
            #pragma unroll
            for (int k = 0; k < 8; k++) {
                float v = ep[(r0 + k) * EPIT + col] + bcol;
                __nv_bfloat16 hv = __float2bfloat16(v);
                float lo = v - __bfloat162float(hv);
                __nv_bfloat16 lv = __float2bfloat16(lo);
                hb[k] = *(unsigned short*)&hv;
                lb[k] = *(unsigned short*)&lv;
            }
            *(uint4*)(oH + r0) = *(uint4*)hb;
            *(uint4*)(oL + r0) = *(uint4*)lb;
        }
    }
}

// ---------------------------------------------------------------------------
// Scores: Sc[b] tile = (Q/32)[m0:,:] K^T[n0:,:]  (causal tiles only, fp32 out)
// ---------------------------------------------------------------------------
__global__ __launch_bounds__(NTHR, 1) void scores_mma(
    const __nv_bfloat16* __restrict__ Qh, const __nv_bfloat16* __restrict__ Ql,
    const __nv_bfloat16* __restrict__ Kh, const __nv_bfloat16* __restrict__ Kl,
    float* __restrict__ Sc)
{
    extern __shared__ __align__(1024) char smem[];
    const int b = blockIdx.z;
    const int m0 = blockIdx.y * TM, n0 = blockIdx.x * TN;
    if (n0 > m0) return;

    const size_t boff = (size_t)b * S * E;
    gemm_core(Qh + boff, Ql + boff, Kh + boff, Kl + boff, m0, n0, E, E, E / KB, smem);
    const float* ep = (const float*)smem;
    float* oF = Sc + (size_t)b * S * S;
    const int tid = threadIdx.x;
    #pragma unroll
    for (int i = 0; i < 32; i++) {
        int idx = tid + NTHR * i;
        int r = idx >> 5, c4 = (idx & 31) * 4;
        float4 o;
        o.x = ep[r * EPIT + c4 + 0];
        o.y = ep[r * EPIT + c4 + 1];
        o.z = ep[r * EPIT + c4 + 2];
        o.w = ep[r * EPIT + c4 + 3];
        *(float4*)&oF[(size_t)(m0 + r) * S + n0 + c4] = o;
    }
}

// ---------------------------------------------------------------------------
// attn_out = P @ V (K clipped at diagonal tile), bf16-pair out
// ---------------------------------------------------------------------------
__global__ __launch_bounds__(NTHR, 1) void attnv_mma(
    const __nv_bfloat16* __restrict__ Ph, const __nv_bfloat16* __restrict__ Pl,
    const __nv_bfloat16* __restrict__ Vth, const __nv_bfloat16* __restrict__ Vtl,
    __nv_bfloat16* AOh, __nv_bfloat16* AOl)
{
    extern __shared__ __align__(1024) char smem[];
    const int b = blockIdx.z;
    const int m0 = blockIdx.y * TM, n0 = blockIdx.x * TN;
    const size_t poff = (size_t)b * S * S, voff = (size_t)b * E * S;

    gemm_core(Ph + poff, Pl + poff, Vth + voff, Vtl + voff,
              m0, n0, S, S, (m0 + TM) / KB, smem);
    const float* ep = (const float*)smem;
    store_pair(ep, nullptr, 1.0f, AOh + (size_t)b * S * E, AOl + (size_t)b * S * E,
               m0, n0, E);
}

// ---------------------------------------------------------------------------
// Output projection: out = AO @ Wo^T + bo (fp32)
// ---------------------------------------------------------------------------
__global__ __launch_bounds__(NTHR, 1) void outproj_mma(
    const __nv_bfloat16* __restrict__ AOh, const __nv_bfloat16* __restrict__ AOl,
    const __nv_bfloat16* __restrict__ woh, const __nv_bfloat16* __restrict__ wol,
    const float* __restrict__ bo, float* __restrict__ out)
{
    extern __shared__ __align__(1024) char smem[];
    const int m0 = blockIdx.y * TM, n0 = blockIdx.x * TN;
    gemm_core(AOh, AOl, woh, wol, m0, n0, E, E, E / KB, smem);
    const float* ep = (const float*)smem;
    const int tid = threadIdx.x;
    #pragma unroll
    for (int i = 0; i < 32; i++) {
        int idx = tid + NTHR * i;
        int r = idx >> 5, c4 = (idx & 31) * 4;
        float4 bv = *(const float4*)&bo[n0 + c4];
        float4 o;
        o.x = ep[r * EPIT + c4 + 0] + bv.x;
        o.y = ep[r * EPIT + c4 + 1] + bv.y;
        o.z = ep[r * EPIT + c4 + 2] + bv.z;
        o.w = ep[r * EPIT + c4 + 3] + bv.w;
        *(float4*)&out[(size_t)(m0 + r) * E + n0 + c4] = o;
    }
}

// ---------------------------------------------------------------------------
// Host launcher
// ---------------------------------------------------------------------------
extern "C" void kernel_launch(void* const* d_in, const int* in_sizes, int n_in,
                              void* d_out, int out_size)
{
    const float* query = (const float*)d_in[0];
    const float* key_  = (const float*)d_in[1];
    const float* value = (const float*)d_in[2];
    const float* Wq = (const float*)d_in[4];
    const float* bq = (const float*)d_in[5];
    const float* Wk = (const float*)d_in[6];
    const float* bk = (const float*)d_in[7];
    const float* Wv = (const float*)d_in[8];
    const float* bv = (const float*)d_in[9];
    const float* Wo = (const float*)d_in[10];
    const float* bo = (const float*)d_in[11];
    float* out = (float*)d_out;

    #define SYM(p, s) void* p; cudaGetSymbolAddress(&p, s)
    SYM(qh, g_qh); SYM(ql, g_ql); SYM(kh, g_kh); SYM(kl, g_kl); SYM(vh, g_vh); SYM(vl, g_vl);
    SYM(wqh, g_wqh); SYM(wql, g_wql); SYM(wkh, g_wkh); SYM(wkl, g_wkl);
    SYM(wvh, g_wvh); SYM(wvl, g_wvl); SYM(woh, g_woh); SYM(wol, g_wol);
    SYM(Qh, g_Qh); SYM(Ql, g_Ql); SYM(Kh, g_Kh); SYM(Kl, g_Kl);
    SYM(Vth, g_Vth); SYM(Vtl, g_Vtl);
    SYM(Sc, g_Sc); SYM(Ph, g_Ph); SYM(Pl, g_Pl); SYM(AOh, g_AOh); SYM(AOl, g_AOl);
    #undef SYM
    typedef __nv_bfloat16 bf;

    cudaFuncSetAttribute((const void*)proj_qkv,    cudaFuncAttributeMaxDynamicSharedMemorySize, SMEM_SZ);
    cudaFuncSetAttribute((const void*)scores_mma,  cudaFuncAttributeMaxDynamicSharedMemorySize, SMEM_SZ);
    cudaFuncSetAttribute((const void*)attnv_mma,   cudaFuncAttributeMaxDynamicSharedMemorySize, SMEM_SZ);
    cudaFuncSetAttribute((const void*)outproj_mma, cudaFuncAttributeMaxDynamicSharedMemorySize, SMEM_SZ);

    // 1) fp32 -> bf16 hi/lo conversions (batched)
    const int nIn = M_ROWS * E, nW = E * E;
    cvt3<<<dim3(nIn / 2048, 3), 256>>>(query, key_, value,
        (bf*)qh, (bf*)ql, (bf*)kh, (bf*)kl, (bf*)vh, (bf*)vl);
    cvt4<<<dim3(nW / 2048, 4), 256>>>(Wq, Wk, Wv, Wo,
        (bf*)wqh, (bf*)wql, (bf*)wkh, (bf*)wkl, (bf*)wvh, (bf*)wvl, (bf*)woh, (bf*)wol);

    // 2) fused Q/K/V projections (Q scaled by 1/32, V transposed)
    proj_qkv<<<dim3(E / TN, M_ROWS / TM, 3), NTHR, SMEM_SZ>>>(
        (bf*)qh, (bf*)ql, (bf*)kh, (bf*)kl, (bf*)vh, (bf*)vl,
        (bf*)wqh, (bf*)wql, (bf*)wkh, (bf*)wkl, (bf*)wvh, (bf*)wvl,
        bq, bk, bv,
        (bf*)Qh, (bf*)Ql, (bf*)Kh, (bf*)Kl, (bf*)Vth, (bf*)Vtl);

    // 3) scores (causal tiles only)
    scores_mma<<<dim3(S / TN, S / TM, B), NTHR, SMEM_SZ>>>(
        (bf*)Qh, (bf*)Ql, (bf*)Kh, (bf*)Kl, (float*)Sc);

    // 4) fused softmax -> bf16-pair P
    softmax_pair<<<B * S, 256>>>((const float*)Sc, (bf*)Ph, (bf*)Pl);

    // 5) attn_out = P @ V
    attnv_mma<<<dim3(E / TN, S / TM, B), NTHR, SMEM_SZ>>>(
        (bf*)Ph, (bf*)Pl, (bf*)Vth, (bf*)Vtl, (bf*)AOh, (bf*)AOl);

    // 6) output projection -> d_out
    outproj_mma<<<dim3(E / TN, M_ROWS / TM, 1), NTHR, SMEM_SZ>>>(
        (bf*)AOh, (bf*)AOl, (bf*)woh, (bf*)wol, bo, out);
}

// round 11
// speedup vs baseline: 1.0604x; 1.0604x over previous
#include <cuda_runtime.h>
#include <cuda_bf16.h>
#include <cstdint>
#include <math.h>

// ---------------------------------------------------------------------------
// Problem constants
// ---------------------------------------------------------------------------
constexpr int B = 4;
constexpr int S = 2048;
constexpr int E = 1024;
constexpr int M_ROWS = B * S;   // 8192

// GEMM tiling: CTA 128x128 (8 warps of 64x32), KB=64 bf16 per chunk
constexpr int TM = 128, TN = 128, KB = 64;
constexpr int NTHR = 256;
constexpr int TILE_BYTES = 128 * 128;          // 16KB per operand tile
constexpr int STAGE_BYTES = 4 * TILE_BYTES;    // Ah, Al, Bh, Bl = 64KB
constexpr int NSTAGE = 3;
constexpr int SMEM_SZ = NSTAGE * STAGE_BYTES;  // 192KB
constexpr int EPIT = 132;                      // fp32 epilogue pitch (words)

// ---------------------------------------------------------------------------
// Scratch (device globals — no allocations allowed)
// ---------------------------------------------------------------------------
__device__ __nv_bfloat16 g_qh[(size_t)M_ROWS * E], g_ql[(size_t)M_ROWS * E];
__device__ __nv_bfloat16 g_kh[(size_t)M_ROWS * E], g_kl[(size_t)M_ROWS * E];
__device__ __nv_bfloat16 g_vh[(size_t)M_ROWS * E], g_vl[(size_t)M_ROWS * E];
__device__ __nv_bfloat16 g_wqh[(size_t)E * E], g_wql[(size_t)E * E];
__device__ __nv_bfloat16 g_wkh[(size_t)E * E], g_wkl[(size_t)E * E];
__device__ __nv_bfloat16 g_wvh[(size_t)E * E], g_wvl[(size_t)E * E];
__device__ __nv_bfloat16 g_woh[(size_t)E * E], g_wol[(size_t)E * E];
__device__ __nv_bfloat16 g_Qh[(size_t)M_ROWS * E], g_Ql[(size_t)M_ROWS * E];
__device__ __nv_bfloat16 g_Kh[(size_t)M_ROWS * E], g_Kl[(size_t)M_ROWS * E];
__device__ __nv_bfloat16 g_Vth[(size_t)B * E * S], g_Vtl[(size_t)B * E * S];
__device__ float         g_Sc[(size_t)B * S * S];
__device__ __nv_bfloat16 g_Ph[(size_t)B * S * S], g_Pl[(size_t)B * S * S];
__device__ __nv_bfloat16 g_AOh[(size_t)M_ROWS * E], g_AOl[(size_t)M_ROWS * E];

// ---------------------------------------------------------------------------
// PTX helpers (Ampere-compatible only: cp.async, ldmatrix, mma.sync)
// ---------------------------------------------------------------------------
__device__ __forceinline__ uint32_t smem_u32(const void* p) {
    uint32_t a;
    asm("{ .reg .u64 t; cvta.to.shared.u64 t, %1; cvt.u32.u64 %0, t; }" : "=r"(a) : "l"(p));
    return a;
}
#define SWZ(o) ((uint32_t)(o) ^ ((((uint32_t)(o)) >> 3) & 0x70))

#define CP_ASYNC16(dst, src) \
    asm volatile("cp.async.cg.shared.global [%0], [%1], 16;" :: "r"(dst), "l"(src) : "memory")
#define CP_COMMIT() asm volatile("cp.async.commit_group;" ::: "memory")
#define CP_WAIT0()  asm volatile("cp.async.wait_group 0;" ::: "memory")
#define CP_WAIT1()  asm volatile("cp.async.wait_group 1;" ::: "memory")

#define LDSM4(r0, r1, r2, r3, a) \
    asm volatile("ldmatrix.sync.aligned.m8n8.x4.shared.b16 {%0,%1,%2,%3}, [%4];" \
                 : "=r"(r0), "=r"(r1), "=r"(r2), "=r"(r3) : "r"(a))

#define MMA16816(c, a, b0, b1) \
    asm volatile("mma.sync.aligned.m16n8k16.row.col.f32.bf16.bf16.f32 " \
                 "{%0,%1,%2,%3},{%4,%5,%6,%7},{%8,%9},{%0,%1,%2,%3};" \
                 : "+f"((c)[0]), "+f"((c)[1]), "+f"((c)[2]), "+f"((c)[3]) \
                 : "r"((a)[0]), "r"((a)[1]), "r"((a)[2]), "r"((a)[3]), \
                   "r"(b0), "r"(b1))

// ---------------------------------------------------------------------------
// Batched fp32 -> (bf16 hi, bf16 lo) conversions (blockIdx.y selects tensor)
// ---------------------------------------------------------------------------
__device__ __forceinline__ void cvt_body(const float* __restrict__ in,
                                         __nv_bfloat16* __restrict__ h,
                                         __nv_bfloat16* __restrict__ l)
{
    int i = (blockIdx.x * 256 + threadIdx.x) * 8;
    float4 a = *(const float4*)(in + i);
    float4 b2 = *(const float4*)(in + i + 4);
    float v[8] = {a.x, a.y, a.z, a.w, b2.x, b2.y, b2.z, b2.w};
    unsigned short hb[8], lb[8];
    #pragma unroll
    for (int j = 0; j < 8; j++) {
        __nv_bfloat16 hv = __float2bfloat16(v[j]);
        float lo = v[j] - __bfloat162float(hv);
        __nv_bfloat16 lv = __float2bfloat16(lo);
        hb[j] = *(unsigned short*)&hv;
        lb[j] = *(unsigned short*)&lv;
    }
    *(uint4*)(h + i) = *(uint4*)hb;
    *(uint4*)(l + i) = *(uint4*)lb;
}

__global__ __launch_bounds__(256) void cvt3(
    const float* __restrict__ i0, const float* __restrict__ i1, const float* __restrict__ i2,
    __nv_bfloat16* h0, __nv_bfloat16* l0, __nv_bfloat16* h1, __nv_bfloat16* l1,
    __nv_bfloat16* h2, __nv_bfloat16* l2)
{
    const int z = blockIdx.y;
    const float* in = (z == 0) ? i0 : (z == 1) ? i1 : i2;
    __nv_bfloat16* h = (z == 0) ? h0 : (z == 1) ? h1 : h2;
    __nv_bfloat16* l = (z == 0) ? l0 : (z == 1) ? l1 : l2;
    cvt_body(in, h, l);
}

__global__ __launch_bounds__(256) void cvt4(
    const float* __restrict__ i0, const float* __restrict__ i1,
    const float* __restrict__ i2, const float* __restrict__ i3,
    __nv_bfloat16* h0, __nv_bfloat16* l0, __nv_bfloat16* h1, __nv_bfloat16* l1,
    __nv_bfloat16* h2, __nv_bfloat16* l2, __nv_bfloat16* h3, __nv_bfloat16* l3)
{
    const int z = blockIdx.y;
    const float* in = (z == 0) ? i0 : (z == 1) ? i1 : (z == 2) ? i2 : i3;
    __nv_bfloat16* h = (z == 0) ? h0 : (z == 1) ? h1 : (z == 2) ? h2 : h3;
    __nv_bfloat16* l = (z == 0) ? l0 : (z == 1) ? l1 : (z == 2) ? l2 : l3;
    cvt_body(in, h, l);
}

// ---------------------------------------------------------------------------
// Fused causal softmax: fp32 scores -> bf16-pair probabilities (zeros padded
// to the 128-multiple so attn@V can run dense up to the diagonal tile).
// ---------------------------------------------------------------------------
__global__ __launch_bounds__(256) void softmax_pair(const float* __restrict__ Sc,
                                                    __nv_bfloat16* __restrict__ Ph,
                                                    __nv_bfloat16* __restrict__ Pl)
{
    const int row = blockIdx.x;
    const int b = row >> 11, q = row & (S - 1);
    const float* ptr = Sc + (size_t)b * S * S + (size_t)q * S;
    const int len = q + 1;
    const int plen = ((q >> 7) + 1) << 7;
    const int tid = threadIdx.x;

    float vals[8];
    float m = -INFINITY;
    #pragma unroll
    for (int i = 0; i < 8; i++) {
        int k = tid + i * 256;
        vals[i] = (k < len) ? ptr[k] : -INFINITY;
        m = fmaxf(m, vals[i]);
    }
    __shared__ float red[256];
    red[tid] = m;
    __syncthreads();
    for (int s = 128; s > 0; s >>= 1) {
        if (tid < s) red[tid] = fmaxf(red[tid], red[tid + s]);
        __syncthreads();
    }
    m = red[0];
    __syncthreads();
    float sum = 0.f;
    #pragma unroll
    for (int i = 0; i < 8; i++) {
        int k = tid + i * 256;
        vals[i] = (k < len) ? __expf(vals[i] - m) : 0.f;
        sum += vals[i];
    }
    red[tid] = sum;
    __syncthreads();
    for (int s = 128; s > 0; s >>= 1) {
        if (tid < s) red[tid] += red[tid + s];
        __syncthreads();
    }
    const float inv = 1.0f / red[0];

    __nv_bfloat16* ph = Ph + (size_t)b * S * S + (size_t)q * S;
    __nv_bfloat16* pl = Pl + (size_t)b * S * S + (size_t)q * S;
    #pragma unroll
    for (int i = 0; i < 8; i++) {
        int k = tid + i * 256;
        if (k < plen) {
            float p = vals[i] * inv;
            __nv_bfloat16 h = __float2bfloat16(p);
            ph[k] = h;
            pl[k] = __float2bfloat16(p - __bfloat162float(h));
        }
    }
}

// ---------------------------------------------------------------------------
// GEMM core (R6 geometry + term-major MMA ordering): 128x128 fp32 tile of
// A[M,K]*Bop[N,K]^T (split-bf16, 3 terms), result in smem ep[128][EPIT].
// 8 warps of 64x32, m16n8k16 via ldmatrix, 3-stage cp.async pipeline.
// Term-major ordering spaces same-accumulator MMAs 16 apart (covers HMMA
// latency with 2 warps/SMSP).
// ---------------------------------------------------------------------------
__device__ __forceinline__ void gemm_core(
    const __nv_bfloat16* __restrict__ Ah, const __nv_bfloat16* __restrict__ Al,
    const __nv_bfloat16* __restrict__ Bh, const __nv_bfloat16* __restrict__ Bl,
    int m0, int n0, int lda, int ldb, int NC, char* smem)
{
    const uint32_t smb = smem_u32(smem);
    const int tid = threadIdx.x;
    const int wid = tid >> 5, lane = tid & 31;
    const int warp_m = wid >> 2;        // 0..1 -> 64-row half
    const int warp_n = wid & 3;         // 0..3 -> 32-col quarter

    auto load_chunk = [&](int c, int s) {
        const int k0 = c * KB;
        const uint32_t stage = smb + s * STAGE_BYTES;
        const __nv_bfloat16* gp[4] = {Ah, Al, Bh, Bl};
        #pragma unroll
        for (int t = 0; t < 4; t++) {
            const __nv_bfloat16* g = gp[t];
            const int r0 = (t < 2) ? m0 : n0;
            const int ld = (t < 2) ? lda : ldb;
            const uint32_t tbase = stage + t * TILE_BYTES;
            #pragma unroll
            for (int i = 0; i < 4; i++) {
                int sg = tid + 256 * i;
                int r = sg >> 3, sc = sg & 7;
                CP_ASYNC16(tbase + SWZ(r * 128 + sc * 16),
                           g + (size_t)(r0 + r) * ld + k0 + sc * 8);
            }
        }
        CP_COMMIT();
    };

    float acc[4][4][4] = {};

    load_chunk(0, 0);
    if (NC > 1) load_chunk(1, 1);

    const int lg = lane >> 3, lr = lane & 7;
    const int rowA = warp_m * 64 + lr + (lg & 1) * 8;
    const int kA   = (lg >> 1) * 16;
    const int rowB = warp_n * 32 + lr + (lg >> 1) * 8;
    const int kBo  = (lg & 1) * 16;

    for (int c = 0; c < NC; c++) {
        if (c == NC - 1) { CP_WAIT0(); } else { CP_WAIT1(); }
        __syncthreads();
        if (c + 2 < NC) load_chunk(c + 2, (c + 2) % NSTAGE);

        const uint32_t stage = smb + (c % NSTAGE) * STAGE_BYTES;
        const uint32_t aH = stage, aL = stage + TILE_BYTES;
        const uint32_t bH = stage + 2 * TILE_BYTES, bL = stage + 3 * TILE_BYTES;

        #pragma unroll
        for (int ks = 0; ks < 4; ks++) {
            const int koA = ks * 32 + kA;
            const int koB = ks * 32 + kBo;
            uint32_t ah[4][4], al[4][4], bh[2][4], bl[2][4];
            #pragma unroll
            for (int i = 0; i < 4; i++) {
                uint32_t off = SWZ((rowA + i * 16) * 128 + koA);
                LDSM4(ah[i][0], ah[i][1], ah[i][2], ah[i][3], aH + off);
                LDSM4(al[i][0], al[i][1], al[i][2], al[i][3], aL + off);
            }
            #pragma unroll
            for (int p = 0; p < 2; p++) {
                uint32_t off = SWZ((rowB + p * 16) * 128 + koB);
                LDSM4(bh[p][0], bh[p][1], bh[p][2], bh[p][3], bH + off);
                LDSM4(bl[p][0], bl[p][1], bl[p][2], bl[p][3], bL + off);
            }
            // term-major: each accumulator is touched once per 16-MMA sweep,
            // so the dependent reuse is ~16 issue slots away.
            #pragma unroll
            for (int i = 0; i < 4; i++)
                #pragma unroll
                for (int j = 0; j < 4; j++) {
                    const int p = j >> 1, h = (j & 1) * 2;
                    MMA16816(acc[i][j], ah[i], bh[p][h], bh[p][h + 1]);
                }
            #pragma unroll
            for (int i = 0; i < 4; i++)
                #pragma unroll
                for (int j = 0; j < 4; j++) {
                    const int p = j >> 1, h = (j & 1) * 2;
                    MMA16816(acc[i][j], al[i], bh[p][h], bh[p][h + 1]);
                }
            #pragma unroll
            for (int i = 0; i < 4; i++)
                #pragma unroll
                for (int j = 0; j < 4; j++) {
                    const int p = j >> 1, h = (j & 1) * 2;
                    MMA16816(acc[i][j], ah[i], bl[p][h], bl[p][h + 1]);
                }
        }
        __syncthreads();
    }

    // regs -> smem ep
    float* ep = (float*)smem;
    const int erow = lane >> 2;
    const int ecol = (lane & 3) * 2;
    #pragma unroll
    for (int i = 0; i < 4; i++) {
        int rbase = warp_m * 64 + i * 16 + erow;
        #pragma unroll
        for (int j = 0; j < 4; j++) {
            int cc = warp_n * 32 + j * 8 + ecol;
            ep[rbase * EPIT + cc]           = acc[i][j][0];
            ep[rbase * EPIT + cc + 1]       = acc[i][j][1];
            ep[(rbase + 8) * EPIT + cc]     = acc[i][j][2];
            ep[(rbase + 8) * EPIT + cc + 1] = acc[i][j][3];
        }
    }
    __syncthreads();
}

// bf16-pair store helper: ep[128][EPIT] (+bias)*scale -> row-major pair arrays
__device__ __forceinline__ void store_pair(
    const float* ep, const float* bias, float scale,
    __nv_bfloat16* oH, __nv_bfloat16* oL, int m0, int n0, int ldc)
{
    const int tid = threadIdx.x;
    #pragma unroll
    for (int i = 0; i < 8; i++) {
        int idx = tid + NTHR * i;
        int r = idx >> 4, c8 = (idx & 15) * 8;
        unsigned short hb[8], lb[8];
        #pragma unroll
        for (int j = 0; j < 8; j++) {
            float v = ep[r * EPIT + c8 + j];
            if (bias) v = (v + bias[n0 + c8 + j]) * scale;
            __nv_bfloat16 hv = __float2bfloat16(v);
            float lo = v - __bfloat162float(hv);
            __nv_bfloat16 lv = __float2bfloat16(lo);
            hb[j] = *(unsigned short*)&hv;
            lb[j] = *(unsigned short*)&lv;
        }
        size_t off = (size_t)(m0 + r) * ldc + n0 + c8;
        *(uint4*)(oH + off) = *(uint4*)hb;
        *(uint4*)(oL + off) = *(uint4*)lb;
    }
}

// ---------------------------------------------------------------------------
// Fused Q/K/V projection: blockIdx.z selects tensor. Q folds the 1/32 scale;
// V writes directly in transposed [b][e][s] bf16-pair layout.
// ---------------------------------------------------------------------------
__global__ __launch_bounds__(NTHR, 1) void proj_qkv(
    const __nv_bfloat16* __restrict__ qh, const __nv_bfloat16* __restrict__ ql,
    const __nv_bfloat16* __restrict__ kh, const __nv_bfloat16* __restrict__ kl,
    const __nv_bfloat16* __restrict__ vh, const __nv_bfloat16* __restrict__ vl,
    const __nv_bfloat16* __restrict__ wqh, const __nv_bfloat16* __restrict__ wql,
    const __nv_bfloat16* __restrict__ wkh, const __nv_bfloat16* __restrict__ wkl,
    const __nv_bfloat16* __restrict__ wvh, const __nv_bfloat16* __restrict__ wvl,
    const float* __restrict__ bq, const float* __restrict__ bk, const float* __restrict__ bv,
    __nv_bfloat16* Qh, __nv_bfloat16* Ql, __nv_bfloat16* Kh, __nv_bfloat16* Kl,
    __nv_bfloat16* Vth, __nv_bfloat16* Vtl)
{
    extern __shared__ __align__(1024) char smem[];
    const int z = blockIdx.z;
    const int m0 = blockIdx.y * TM, n0 = blockIdx.x * TN;

    const __nv_bfloat16 *Ah, *Al, *Bh, *Bl;
    const float* bias;
    if (z == 0)      { Ah = qh; Al = ql; Bh = wqh; Bl = wql; bias = bq; }
    else if (z == 1) { Ah = kh; Al = kl; Bh = wkh; Bl = wkl; bias = bk; }
    else             { Ah = vh; Al = vl; Bh = wvh; Bl = wvl; bias = bv; }

    gemm_core(Ah, Al, Bh, Bl, m0, n0, E, E, E / KB, smem);
    const float* ep = (const float*)smem;
    const int tid = threadIdx.x;

    if (z == 0) {
        store_pair(ep, bias, 0.03125f, Qh, Ql, m0, n0, E);
    } else if (z == 1) {
        store_pair(ep, bias, 1.0f, Kh, Kl, m0, n0, E);
    } else {
        // transposed store: V[m0+r][n0+col] -> Vt[b][n0+col][s0+r]
        const int bb = m0 >> 11;
        const int s0 = m0 & (S - 1);
        const int col = tid & 127, half = tid >> 7;   // rows 0-63 / 64-127
        const float bcol = bias[n0 + col];
        __nv_bfloat16* oH = Vth + ((size_t)bb * E + n0 + col) * S + s0 + half * 64;
        __nv_bfloat16* oL = Vtl + ((size_t)bb * E + n0 + col) * S + s0 + half * 64;
        #pragma unroll
        for (int r0 = 0; r0 < 64; r0 += 8) {
            unsigned short hb[8], lb[8];
            #pragma unroll
            for (int k = 0; k < 8; k++) {
                float v = ep[(half * 64 + r0 + k) * EPIT + col] + bcol;
                __nv_bfloat16 hv = __float2bfloat16(v);
                float lo = v - __bfloat162float(hv);
                __nv_bfloat16 lv = __float2bfloat16(lo);
                hb[k] = *(unsigned short*)&hv;
                lb[k] = *(unsigned short*)&lv;
            }
            *(uint4*)(oH + r0) = *(uint4*)hb;
            *(uint4*)(oL + r0) = *(uint4*)lb;
        }
    }
}

// ---------------------------------------------------------------------------
// Scores: Sc[b] tile = (Q/32)[m0:,:] K^T[n0:,:]  (causal tiles only, fp32 out)
// ---------------------------------------------------------------------------
__global__ __launch_bounds__(NTHR, 1) void scores_mma(
    const __nv_bfloat16* __restrict__ Qh, const __nv_bfloat16* __restrict__ Ql,
    const __nv_bfloat16* __restrict__ Kh, const __nv_bfloat16* __restrict__ Kl,
    float* __restrict__ Sc)
{
    extern __shared__ __align__(1024) char smem[];
    const int b = blockIdx.z;
    const int m0 = blockIdx.y * TM, n0 = blockIdx.x * TN;
    if (n0 > m0) return;

    const size_t boff = (size_t)b * S * E;
    gemm_core(Qh + boff, Ql + boff, Kh + boff, Kl + boff, m0, n0, E, E, E / KB, smem);
    const float* ep = (const float*)smem;
    float* oF = Sc + (size_t)b * S * S;
    const int tid = threadIdx.x;
    #pragma unroll
    for (int i = 0; i < 16; i++) {
        int idx = tid + NTHR * i;
        int r = idx >> 5, c4 = (idx & 31) * 4;
        float4 o;
        o.x = ep[r * EPIT + c4 + 0];
        o.y = ep[r * EPIT + c4 + 1];
        o.z = ep[r * EPIT + c4 + 2];
        o.w = ep[r * EPIT + c4 + 3];
        *(float4*)&oF[(size_t)(m0 + r) * S + n0 + c4] = o;
    }
}

// ---------------------------------------------------------------------------
// attn_out = P @ V (K clipped at diagonal tile), bf16-pair out
// ---------------------------------------------------------------------------
__global__ __launch_bounds__(NTHR, 1) void attnv_mma(
    const __nv_bfloat16* __restrict__ Ph, const __nv_bfloat16* __restrict__ Pl,
    const __nv_bfloat16* __restrict__ Vth, const __nv_bfloat16* __restrict__ Vtl,
    __nv_bfloat16* AOh, __nv_bfloat16* AOl)
{
    extern __shared__ __align__(1024) char smem[];
    const int b = blockIdx.z;
    const int m0 = blockIdx.y * TM, n0 = blockIdx.x * TN;
    const size_t poff = (size_t)b * S * S, voff = (size_t)b * E * S;

    gemm_core(Ph + poff, Pl + poff, Vth + voff, Vtl + voff,
              m0, n0, S, S, (m0 + TM) / KB, smem);
    const float* ep = (const float*)smem;
    store_pair(ep, nullptr, 1.0f, AOh + (size_t)b * S * E, AOl + (size_t)b * S * E,
               m0, n0, E);
}

// ---------------------------------------------------------------------------
// Output projection: out = AO @ Wo^T + bo (fp32)
// ---------------------------------------------------------------------------
__global__ __launch_bounds__(NTHR, 1) void outproj_mma(
    const __nv_bfloat16* __restrict__ AOh, const __nv_bfloat16* __restrict__ AOl,
    const __nv_bfloat16* __restrict__ woh, const __nv_bfloat16* __restrict__ wol,
    const float* __restrict__ bo, float* __restrict__ out)
{
    extern __shared__ __align__(1024) char smem[];
    const int m0 = blockIdx.y * TM, n0 = blockIdx.x * TN;
    gemm_core(AOh, AOl, woh, wol, m0, n0, E, E, E / KB, smem);
    const float* ep = (const float*)smem;
    const int tid = threadIdx.x;
    #pragma unroll
    for (int i = 0; i < 16; i++) {
        int idx = tid + NTHR * i;
        int r = idx >> 5, c4 = (idx & 31) * 4;
        float4 bv = *(const float4*)&bo[n0 + c4];
        float4 o;
        o.x = ep[r * EPIT + c4 + 0] + bv.x;
        o.y = ep[r * EPIT + c4 + 1] + bv.y;
        o.z = ep[r * EPIT + c4 + 2] + bv.z;
        o.w = ep[r * EPIT + c4 + 3] + bv.w;
        *(float4*)&out[(size_t)(m0 + r) * E + n0 + c4] = o;
    }
}

// ---------------------------------------------------------------------------
// Host launcher
// ---------------------------------------------------------------------------
extern "C" void kernel_launch(void* const* d_in, const int* in_sizes, int n_in,
                              void* d_out, int out_size)
{
    const float* query = (const float*)d_in[0];
    const float* key_  = (const float*)d_in[1];
    const float* value = (const float*)d_in[2];
    const float* Wq = (const float*)d_in[4];
    const float* bq = (const float*)d_in[5];
    const float* Wk = (const float*)d_in[6];
    const float* bk = (const float*)d_in[7];
    const float* Wv = (const float*)d_in[8];
    const float* bv = (const float*)d_in[9];
    const float* Wo = (const float*)d_in[10];
    const float* bo = (const float*)d_in[11];
    float* out = (float*)d_out;

    #define SYM(p, s) void* p; cudaGetSymbolAddress(&p, s)
    SYM(qh, g_qh); SYM(ql, g_ql); SYM(kh, g_kh); SYM(kl, g_kl); SYM(vh, g_vh); SYM(vl, g_vl);
    SYM(wqh, g_wqh); SYM(wql, g_wql); SYM(wkh, g_wkh); SYM(wkl, g_wkl);
    SYM(wvh, g_wvh); SYM(wvl, g_wvl); SYM(woh, g_woh); SYM(wol, g_wol);
    SYM(Qh, g_Qh); SYM(Ql, g_Ql); SYM(Kh, g_Kh); SYM(Kl, g_Kl);
    SYM(Vth, g_Vth); SYM(Vtl, g_Vtl);
    SYM(Sc, g_Sc); SYM(Ph, g_Ph); SYM(Pl, g_Pl); SYM(AOh, g_AOh); SYM(AOl, g_AOl);
    #undef SYM
    typedef __nv_bfloat16 bf;

    cudaFuncSetAttribute((const void*)proj_qkv,    cudaFuncAttributeMaxDynamicSharedMemorySize, SMEM_SZ);
    cudaFuncSetAttribute((const void*)scores_mma,  cudaFuncAttributeMaxDynamicSharedMemorySize, SMEM_SZ);
    cudaFuncSetAttribute((const void*)attnv_mma,   cudaFuncAttributeMaxDynamicSharedMemorySize, SMEM_SZ);
    cudaFuncSetAttribute((const void*)outproj_mma, cudaFuncAttributeMaxDynamicSharedMemorySize, SMEM_SZ);

    // 1) fp32 -> bf16 hi/lo conversions (batched)
    const int nIn = M_ROWS * E, nW = E * E;
    cvt3<<<dim3(nIn / 2048, 3), 256>>>(query, key_, value,
        (bf*)qh, (bf*)ql, (bf*)kh, (bf*)kl, (bf*)vh, (bf*)vl);
    cvt4<<<dim3(nW / 2048, 4), 256>>>(Wq, Wk, Wv, Wo,
        (bf*)wqh, (bf*)wql, (bf*)wkh, (bf*)wkl, (bf*)wvh, (bf*)wvl, (bf*)woh, (bf*)wol);

    // 2) fused Q/K/V projections (Q scaled by 1/32, V transposed)
    proj_qkv<<<dim3(E / TN, M_ROWS / TM, 3), NTHR, SMEM_SZ>>>(
        (bf*)qh, (bf*)ql, (bf*)kh, (bf*)kl, (bf*)vh, (bf*)vl,
        (bf*)wqh, (bf*)wql, (bf*)wkh, (bf*)wkl, (bf*)wvh, (bf*)wvl,
        bq, bk, bv,
        (bf*)Qh, (bf*)Ql, (bf*)Kh, (bf*)Kl, (bf*)Vth, (bf*)Vtl);

    // 3) scores (causal tiles only)
    scores_mma<<<dim3(S / TN, S / TM, B), NTHR, SMEM_SZ>>>(
        (bf*)Qh, (bf*)Ql, (bf*)Kh, (bf*)Kl, (float*)Sc);

    // 4) fused softmax -> bf16-pair P
    softmax_pair<<<B * S, 256>>>((const float*)Sc, (bf*)Ph, (bf*)Pl);

    // 5) attn_out = P @ V
    attnv_mma<<<dim3(E / TN, S / TM, B), NTHR, SMEM_SZ>>>(
        (bf*)Ph, (bf*)Pl, (bf*)Vth, (bf*)Vtl, (bf*)AOh, (bf*)AOl);

    // 6) output projection -> d_out
    outproj_mma<<<dim3(E / TN, M_ROWS / TM, 1), NTHR, SMEM_SZ>>>(
        (bf*)AOh, (bf*)AOl, (bf*)woh, (bf*)wol, bo, out);
}

// round 12
// speedup vs baseline: 1.0795x; 1.0180x over previous
#include <cuda_runtime.h>
#include <cuda_bf16.h>
#include <cstdint>
#include <math.h>

// ---------------------------------------------------------------------------
// Problem constants
// ---------------------------------------------------------------------------
constexpr int B = 4;
constexpr int S = 2048;
constexpr int E = 1024;
constexpr int M_ROWS = B * S;   // 8192

// GEMM tiling: CTA 128x128 (8 warps of 64x32), KB=64 bf16 per chunk
constexpr int TM = 128, TN = 128, KB = 64;
constexpr int NTHR = 256;
constexpr int TILE_BYTES = 128 * 128;          // 16KB per operand tile
constexpr int STAGE_BYTES = 4 * TILE_BYTES;    // Ah, Al, Bh, Bl = 64KB
constexpr int NSTAGE = 3;
constexpr int SMEM_SZ = NSTAGE * STAGE_BYTES;  // 192KB
constexpr int EPIT = 132;                      // fp32 epilogue pitch (words)

// ---------------------------------------------------------------------------
// Scratch (device globals — no allocations allowed)
// ---------------------------------------------------------------------------
__device__ __nv_bfloat16 g_qh[(size_t)M_ROWS * E], g_ql[(size_t)M_ROWS * E];
__device__ __nv_bfloat16 g_kh[(size_t)M_ROWS * E], g_kl[(size_t)M_ROWS * E];
__device__ __nv_bfloat16 g_vh[(size_t)M_ROWS * E], g_vl[(size_t)M_ROWS * E];
__device__ __nv_bfloat16 g_wqh[(size_t)E * E], g_wql[(size_t)E * E];
__device__ __nv_bfloat16 g_wkh[(size_t)E * E], g_wkl[(size_t)E * E];
__device__ __nv_bfloat16 g_wvh[(size_t)E * E], g_wvl[(size_t)E * E];
__device__ __nv_bfloat16 g_woh[(size_t)E * E], g_wol[(size_t)E * E];
__device__ __nv_bfloat16 g_Qh[(size_t)M_ROWS * E], g_Ql[(size_t)M_ROWS * E];
__device__ __nv_bfloat16 g_Kh[(size_t)M_ROWS * E], g_Kl[(size_t)M_ROWS * E];
__device__ __nv_bfloat16 g_Vth[(size_t)B * E * S], g_Vtl[(size_t)B * E * S];
__device__ float         g_Sc[(size_t)B * S * S];
__device__ __nv_bfloat16 g_Ph[(size_t)B * S * S], g_Pl[(size_t)B * S * S];
__device__ __nv_bfloat16 g_AOh[(size_t)M_ROWS * E], g_AOl[(size_t)M_ROWS * E];

// ---------------------------------------------------------------------------
// PTX helpers (Ampere-compatible only: cp.async, ldmatrix, mma.sync)
// ---------------------------------------------------------------------------
__device__ __forceinline__ uint32_t smem_u32(const void* p) {
    uint32_t a;
    asm("{ .reg .u64 t; cvta.to.shared.u64 t, %1; cvt.u32.u64 %0, t; }" : "=r"(a) : "l"(p));
    return a;
}
#define SWZ(o) ((uint32_t)(o) ^ ((((uint32_t)(o)) >> 3) & 0x70))

#define CP_ASYNC16(dst, src) \
    asm volatile("cp.async.cg.shared.global [%0], [%1], 16;" :: "r"(dst), "l"(src) : "memory")
#define CP_COMMIT() asm volatile("cp.async.commit_group;" ::: "memory")
#define CP_WAIT0()  asm volatile("cp.async.wait_group 0;" ::: "memory")
#define CP_WAIT1()  asm volatile("cp.async.wait_group 1;" ::: "memory")

#define LDSM4(r0, r1, r2, r3, a) \
    asm volatile("ldmatrix.sync.aligned.m8n8.x4.shared.b16 {%0,%1,%2,%3}, [%4];" \
                 : "=r"(r0), "=r"(r1), "=r"(r2), "=r"(r3) : "r"(a))

#define MMA16816(c, a, b0, b1) \
    asm volatile("mma.sync.aligned.m16n8k16.row.col.f32.bf16.bf16.f32 " \
                 "{%0,%1,%2,%3},{%4,%5,%6,%7},{%8,%9},{%0,%1,%2,%3};" \
                 : "+f"((c)[0]), "+f"((c)[1]), "+f"((c)[2]), "+f"((c)[3]) \
                 : "r"((a)[0]), "r"((a)[1]), "r"((a)[2]), "r"((a)[3]), \
                   "r"(b0), "r"(b1))

// ---------------------------------------------------------------------------
// Batched fp32 -> (bf16 hi, bf16 lo) conversions (blockIdx.y selects tensor)
// ---------------------------------------------------------------------------
__device__ __forceinline__ void cvt_body(const float* __restrict__ in,
                                         __nv_bfloat16* __restrict__ h,
                                         __nv_bfloat16* __restrict__ l)
{
    int i = (blockIdx.x * 256 + threadIdx.x) * 8;
    float4 a = *(const float4*)(in + i);
    float4 b2 = *(const float4*)(in + i + 4);
    float v[8] = {a.x, a.y, a.z, a.w, b2.x, b2.y, b2.z, b2.w};
    unsigned short hb[8], lb[8];
    #pragma unroll
    for (int j = 0; j < 8; j++) {
        __nv_bfloat16 hv = __float2bfloat16(v[j]);
        float lo = v[j] - __bfloat162float(hv);
        __nv_bfloat16 lv = __float2bfloat16(lo);
        hb[j] = *(unsigned short*)&hv;
        lb[j] = *(unsigned short*)&lv;
    }
    *(uint4*)(h + i) = *(uint4*)hb;
    *(uint4*)(l + i) = *(uint4*)lb;
}

__global__ __launch_bounds__(256) void cvt3(
    const float* __restrict__ i0, const float* __restrict__ i1, const float* __restrict__ i2,
    __nv_bfloat16* h0, __nv_bfloat16* l0, __nv_bfloat16* h1, __nv_bfloat16* l1,
    __nv_bfloat16* h2, __nv_bfloat16* l2)
{
    const int z = blockIdx.y;
    const float* in = (z == 0) ? i0 : (z == 1) ? i1 : i2;
    __nv_bfloat16* h = (z == 0) ? h0 : (z == 1) ? h1 : h2;
    __nv_bfloat16* l = (z == 0) ? l0 : (z == 1) ? l1 : l2;
    cvt_body(in, h, l);
}

__global__ __launch_bounds__(256) void cvt4(
    const float* __restrict__ i0, const float* __restrict__ i1,
    const float* __restrict__ i2, const float* __restrict__ i3,
    __nv_bfloat16* h0, __nv_bfloat16* l0, __nv_bfloat16* h1, __nv_bfloat16* l1,
    __nv_bfloat16* h2, __nv_bfloat16* l2, __nv_bfloat16* h3, __nv_bfloat16* l3)
{
    const int z = blockIdx.y;
    const float* in = (z == 0) ? i0 : (z == 1) ? i1 : (z == 2) ? i2 : i3;
    __nv_bfloat16* h = (z == 0) ? h0 : (z == 1) ? h1 : (z == 2) ? h2 : h3;
    __nv_bfloat16* l = (z == 0) ? l0 : (z == 1) ? l1 : (z == 2) ? l2 : l3;
    cvt_body(in, h, l);
}

// ---------------------------------------------------------------------------
// Fused causal softmax: fp32 scores -> bf16-pair probabilities (zeros padded
// to the 128-multiple so attn@V can run dense up to the diagonal tile).
// Longest rows launched first.
// ---------------------------------------------------------------------------
__global__ __launch_bounds__(256) void softmax_pair(const float* __restrict__ Sc,
                                                    __nv_bfloat16* __restrict__ Ph,
                                                    __nv_bfloat16* __restrict__ Pl)
{
    const int row = blockIdx.x;
    const int b = row >> 11;
    const int q = (S - 1) - (row & (S - 1));   // descending: long rows first
    const float* ptr = Sc + (size_t)b * S * S + (size_t)q * S;
    const int len = q + 1;
    const int plen = ((q >> 7) + 1) << 7;
    const int tid = threadIdx.x;

    float vals[8];
    float m = -INFINITY;
    #pragma unroll
    for (int i = 0; i < 8; i++) {
        int k = tid + i * 256;
        vals[i] = (k < len) ? ptr[k] : -INFINITY;
        m = fmaxf(m, vals[i]);
    }
    __shared__ float red[256];
    red[tid] = m;
    __syncthreads();
    for (int s = 128; s > 0; s >>= 1) {
        if (tid < s) red[tid] = fmaxf(red[tid], red[tid + s]);
        __syncthreads();
    }
    m = red[0];
    __syncthreads();
    float sum = 0.f;
    #pragma unroll
    for (int i = 0; i < 8; i++) {
        int k = tid + i * 256;
        vals[i] = (k < len) ? __expf(vals[i] - m) : 0.f;
        sum += vals[i];
    }
    red[tid] = sum;
    __syncthreads();
    for (int s = 128; s > 0; s >>= 1) {
        if (tid < s) red[tid] += red[tid + s];
        __syncthreads();
    }
    const float inv = 1.0f / red[0];

    __nv_bfloat16* ph = Ph + (size_t)b * S * S + (size_t)q * S;
    __nv_bfloat16* pl = Pl + (size_t)b * S * S + (size_t)q * S;
    #pragma unroll
    for (int i = 0; i < 8; i++) {
        int k = tid + i * 256;
        if (k < plen) {
            float p = vals[i] * inv;
            __nv_bfloat16 h = __float2bfloat16(p);
            ph[k] = h;
            pl[k] = __float2bfloat16(p - __bfloat162float(h));
        }
    }
}

// ---------------------------------------------------------------------------
// GEMM core: 128x128 fp32 tile of A[M,K]*Bop[N,K]^T (split-bf16, 3 terms),
// result in smem ep[128][EPIT].
// 8 warps of 64x32, m16n8k16 via ldmatrix, 3-stage cp.async pipeline.
// ONE sync per chunk: the leading sync of iteration c+1 already orders all
// warps' reads of stage c%3 before the c+3 load overwrites it, so the old
// trailing sync was redundant.
// ---------------------------------------------------------------------------
__device__ __forceinline__ void gemm_core(
    const __nv_bfloat16* __restrict__ Ah, const __nv_bfloat16* __restrict__ Al,
    const __nv_bfloat16* __restrict__ Bh, const __nv_bfloat16* __restrict__ Bl,
    int m0, int n0, int lda, int ldb, int NC, char* smem)
{
    const uint32_t smb = smem_u32(smem);
    const int tid = threadIdx.x;
    const int wid = tid >> 5, lane = tid & 31;
    const int warp_m = wid >> 2;        // 0..1 -> 64-row half
    const int warp_n = wid & 3;         // 0..3 -> 32-col quarter

    auto load_chunk = [&](int c, int s) {
        const int k0 = c * KB;
        const uint32_t stage = smb + s * STAGE_BYTES;
        const __nv_bfloat16* gp[4] = {Ah, Al, Bh, Bl};
        #pragma unroll
        for (int t = 0; t < 4; t++) {
            const __nv_bfloat16* g = gp[t];
            const int r0 = (t < 2) ? m0 : n0;
            const int ld = (t < 2) ? lda : ldb;
            const uint32_t tbase = stage + t * TILE_BYTES;
            #pragma unroll
            for (int i = 0; i < 4; i++) {
                int sg = tid + 256 * i;
                int r = sg >> 3, sc = sg & 7;
                CP_ASYNC16(tbase + SWZ(r * 128 + sc * 16),
                           g + (size_t)(r0 + r) * ld + k0 + sc * 8);
            }
        }
        CP_COMMIT();
    };

    float acc[4][4][4] = {};

    load_chunk(0, 0);
    if (NC > 1) load_chunk(1, 1);

    const int lg = lane >> 3, lr = lane & 7;
    const int rowA = warp_m * 64 + lr + (lg & 1) * 8;
    const int kA   = (lg >> 1) * 16;
    const int rowB = warp_n * 32 + lr + (lg >> 1) * 8;
    const int kBo  = (lg & 1) * 16;

    for (int c = 0; c < NC; c++) {
        if (c == NC - 1) { CP_WAIT0(); } else { CP_WAIT1(); }
        __syncthreads();
        if (c + 2 < NC) load_chunk(c + 2, (c + 2) % NSTAGE);

        const uint32_t stage = smb + (c % NSTAGE) * STAGE_BYTES;
        const uint32_t aH = stage, aL = stage + TILE_BYTES;
        const uint32_t bH = stage + 2 * TILE_BYTES, bL = stage + 3 * TILE_BYTES;

        #pragma unroll
        for (int ks = 0; ks < 4; ks++) {
            const int koA = ks * 32 + kA;
            const int koB = ks * 32 + kBo;
            uint32_t ah[4][4], al[4][4], bh[2][4], bl[2][4];
            #pragma unroll
            for (int i = 0; i < 4; i++) {
                uint32_t off = SWZ((rowA + i * 16) * 128 + koA);
                LDSM4(ah[i][0], ah[i][1], ah[i][2], ah[i][3], aH + off);
                LDSM4(al[i][0], al[i][1], al[i][2], al[i][3], aL + off);
            }
            #pragma unroll
            for (int p = 0; p < 2; p++) {
                uint32_t off = SWZ((rowB + p * 16) * 128 + koB);
                LDSM4(bh[p][0], bh[p][1], bh[p][2], bh[p][3], bH + off);
                LDSM4(bl[p][0], bl[p][1], bl[p][2], bl[p][3], bL + off);
            }
            #pragma unroll
            for (int i = 0; i < 4; i++)
                #pragma unroll
                for (int j = 0; j < 4; j++) {
                    const int p = j >> 1, h = (j & 1) * 2;
                    MMA16816(acc[i][j], ah[i], bh[p][h], bh[p][h + 1]);
                }
            #pragma unroll
            for (int i = 0; i < 4; i++)
                #pragma unroll
                for (int j = 0; j < 4; j++) {
                    const int p = j >> 1, h = (j & 1) * 2;
                    MMA16816(acc[i][j], al[i], bh[p][h], bh[p][h + 1]);
                }
            #pragma unroll
            for (int i = 0; i < 4; i++)
                #pragma unroll
                for (int j = 0; j < 4; j++) {
                    const int p = j >> 1, h = (j & 1) * 2;
                    MMA16816(acc[i][j], ah[i], bl[p][h], bl[p][h + 1]);
                }
        }
        // no trailing sync: next iteration's leading sync provides the barrier
    }
    __syncthreads();   // all warps done computing before ep overwrites stages

    // regs -> smem ep
    float* ep = (float*)smem;
    const int erow = lane >> 2;
    const int ecol = (lane & 3) * 2;
    #pragma unroll
    for (int i = 0; i < 4; i++) {
        int rbase = warp_m * 64 + i * 16 + erow;
        #pragma unroll
        for (int j = 0; j < 4; j++) {
            int cc = warp_n * 32 + j * 8 + ecol;
            ep[rbase * EPIT + cc]           = acc[i][j][0];
            ep[rbase * EPIT + cc + 1]       = acc[i][j][1];
            ep[(rbase + 8) * EPIT + cc]     = acc[i][j][2];
            ep[(rbase + 8) * EPIT + cc + 1] = acc[i][j][3];
        }
    }
    __syncthreads();
}

// bf16-pair store helper: ep[128][EPIT] (+bias)*scale -> row-major pair arrays
__device__ __forceinline__ void store_pair(
    const float* ep, const float* bias, float scale,
    __nv_bfloat16* oH, __nv_bfloat16* oL, int m0, int n0, int ldc)
{
    const int tid = threadIdx.x;
    #pragma unroll
    for (int i = 0; i < 8; i++) {
        int idx = tid + NTHR * i;
        int r = idx >> 4, c8 = (idx & 15) * 8;
        unsigned short hb[8], lb[8];
        #pragma unroll
        for (int j = 0; j < 8; j++) {
            float v = ep[r * EPIT + c8 + j];
            if (bias) v = (v + bias[n0 + c8 + j]) * scale;
            __nv_bfloat16 hv = __float2bfloat16(v);
            float lo = v - __bfloat162float(hv);
            __nv_bfloat16 lv = __float2bfloat16(lo);
            hb[j] = *(unsigned short*)&hv;
            lb[j] = *(unsigned short*)&lv;
        }
        size_t off = (size_t)(m0 + r) * ldc + n0 + c8;
        *(uint4*)(oH + off) = *(uint4*)hb;
        *(uint4*)(oL + off) = *(uint4*)lb;
    }
}

// ---------------------------------------------------------------------------
// Fused Q/K/V projection: blockIdx.z selects tensor. Q folds the 1/32 scale;
// V writes directly in transposed [b][e][s] bf16-pair layout.
// ---------------------------------------------------------------------------
__global__ __launch_bounds__(NTHR, 1) void proj_qkv(
    const __nv_bfloat16* __restrict__ qh, const __nv_bfloat16* __restrict__ ql,
    const __nv_bfloat16* __restrict__ kh, const __nv_bfloat16* __restrict__ kl,
    const __nv_bfloat16* __restrict__ vh, const __nv_bfloat16* __restrict__ vl,
    const __nv_bfloat16* __restrict__ wqh, const __nv_bfloat16* __restrict__ wql,
    const __nv_bfloat16* __restrict__ wkh, const __nv_bfloat16* __restrict__ wkl,
    const __nv_bfloat16* __restrict__ wvh, const __nv_bfloat16* __restrict__ wvl,
    const float* __restrict__ bq, const float* __restrict__ bk, const float* __restrict__ bv,
    __nv_bfloat16* Qh, __nv_bfloat16* Ql, __nv_bfloat16* Kh, __nv_bfloat16* Kl,
    __nv_bfloat16* Vth, __nv_bfloat16* Vtl)
{
    extern __shared__ __align__(1024) char smem[];
    const int z = blockIdx.z;
    const int m0 = blockIdx.y * TM, n0 = blockIdx.x * TN;

    const __nv_bfloat16 *Ah, *Al, *Bh, *Bl;
    const float* bias;
    if (z == 0)      { Ah = qh; Al = ql; Bh = wqh; Bl = wql; bias = bq; }
    else if (z == 1) { Ah = kh; Al = kl; Bh = wkh; Bl = wkl; bias = bk; }
    else             { Ah = vh; Al = vl; Bh = wvh; Bl = wvl; bias = bv; }

    gemm_core(Ah, Al, Bh, Bl, m0, n0, E, E, E / KB, smem);
    const float* ep = (const float*)smem;
    const int tid = threadIdx.x;

    if (z == 0) {
        store_pair(ep, bias, 0.03125f, Qh, Ql, m0, n0, E);
    } else if (z == 1) {
        store_pair(ep, bias, 1.0f, Kh, Kl, m0, n0, E);
    } else {
        // transposed store: V[m0+r][n0+col] -> Vt[b][n0+col][s0+r]
        const int bb = m0 >> 11;
        const int s0 = m0 & (S - 1);
        const int col = tid & 127, half = tid >> 7;   // rows 0-63 / 64-127
        const float bcol = bias[n0 + col];
        __nv_bfloat16* oH = Vth + ((size_t)bb * E + n0 + col) * S + s0 + half * 64;
        __nv_bfloat16* oL = Vtl + ((size_t)bb * E + n0 + col) * S + s0 + half * 64;
        #pragma unroll
        for (int r0 = 0; r0 < 64; r0 += 8) {
            unsigned short hb[8], lb[8];
            #pragma unroll
            for (int k = 0; k < 8; k++) {
                float v = ep[(half * 64 + r0 + k) * EPIT + col] + bcol;
                __nv_bfloat16 hv = __float2bfloat16(v);
                float lo = v - __bfloat162float(hv);
                __nv_bfloat16 lv = __float2bfloat16(lo);
                hb[k] = *(unsigned short*)&hv;
                lb[k] = *(unsigned short*)&lv;
            }
            *(uint4*)(oH + r0) = *(uint4*)hb;
            *(uint4*)(oL + r0) = *(uint4*)lb;
        }
    }
}

// ---------------------------------------------------------------------------
// Scores: compact triangular grid — blockIdx.x in [0,136) maps to (mi,ni)
// with ni <= mi. No no-op CTAs.
// ---------------------------------------------------------------------------
__global__ __launch_bounds__(NTHR, 1) void scores_mma(
    const __nv_bfloat16* __restrict__ Qh, const __nv_bfloat16* __restrict__ Ql,
    const __nv_bfloat16* __restrict__ Kh, const __nv_bfloat16* __restrict__ Kl,
    float* __restrict__ Sc)
{
    extern __shared__ __align__(1024) char smem[];
    const int b = blockIdx.z;
    const int t = blockIdx.x;
    int mi = (int)((sqrtf(8.0f * (float)t + 1.0f) - 1.0f) * 0.5f);
    while ((mi + 1) * (mi + 2) / 2 <= t) mi++;
    while (mi * (mi + 1) / 2 > t) mi--;
    const int ni = t - mi * (mi + 1) / 2;
    const int m0 = mi * TM, n0 = ni * TN;

    const size_t boff = (size_t)b * S * E;
    gemm_core(Qh + boff, Ql + boff, Kh + boff, Kl + boff, m0, n0, E, E, E / KB, smem);
    const float* ep = (const float*)smem;
    float* oF = Sc + (size_t)b * S * S;
    const int tid = threadIdx.x;
    #pragma unroll
    for (int i = 0; i < 16; i++) {
        int idx = tid + NTHR * i;
        int r = idx >> 5, c4 = (idx & 31) * 4;
        float4 o;
        o.x = ep[r * EPIT + c4 + 0];
        o.y = ep[r * EPIT + c4 + 1];
        o.z = ep[r * EPIT + c4 + 2];
        o.w = ep[r * EPIT + c4 + 3];
        *(float4*)&oF[(size_t)(m0 + r) * S + n0 + c4] = o;
    }
}

// ---------------------------------------------------------------------------
// attn_out = P @ V (K clipped at diagonal tile), bf16-pair out.
// m-tiles remapped descending: longest-running CTAs launch first.
// ---------------------------------------------------------------------------
__global__ __launch_bounds__(NTHR, 1) void attnv_mma(
    const __nv_bfloat16* __restrict__ Ph, const __nv_bfloat16* __restrict__ Pl,
    const __nv_bfloat16* __restrict__ Vth, const __nv_bfloat16* __restrict__ Vtl,
    __nv_bfloat16* AOh, __nv_bfloat16* AOl)
{
    extern __shared__ __align__(1024) char smem[];
    const int b = blockIdx.z;
    const int mi = (gridDim.y - 1) - blockIdx.y;   // longest first
    const int m0 = mi * TM, n0 = blockIdx.x * TN;
    const size_t poff = (size_t)b * S * S, voff = (size_t)b * E * S;

    gemm_core(Ph + poff, Pl + poff, Vth + voff, Vtl + voff,
              m0, n0, S, S, (m0 + TM) / KB, smem);
    const float* ep = (const float*)smem;
    store_pair(ep, nullptr, 1.0f, AOh + (size_t)b * S * E, AOl + (size_t)b * S * E,
               m0, n0, E);
}

// ---------------------------------------------------------------------------
// Output projection: out = AO @ Wo^T + bo (fp32)
// ---------------------------------------------------------------------------
__global__ __launch_bounds__(NTHR, 1) void outproj_mma(
    const __nv_bfloat16* __restrict__ AOh, const __nv_bfloat16* __restrict__ AOl,
    const __nv_bfloat16* __restrict__ woh, const __nv_bfloat16* __restrict__ wol,
    const float* __restrict__ bo, float* __restrict__ out)
{
    extern __shared__ __align__(1024) char smem[];
    const int m0 = blockIdx.y * TM, n0 = blockIdx.x * TN;
    gemm_core(AOh, AOl, woh, wol, m0, n0, E, E, E / KB, smem);
    const float* ep = (const float*)smem;
    const int tid = threadIdx.x;
    #pragma unroll
    for (int i = 0; i < 16; i++) {
        int idx = tid + NTHR * i;
        int r = idx >> 5, c4 = (idx & 31) * 4;
        float4 bv = *(const float4*)&bo[n0 + c4];
        float4 o;
        o.x = ep[r * EPIT + c4 + 0] + bv.x;
        o.y = ep[r * EPIT + c4 + 1] + bv.y;
        o.z = ep[r * EPIT + c4 + 2] + bv.z;
        o.w = ep[r * EPIT + c4 + 3] + bv.w;
        *(float4*)&out[(size_t)(m0 + r) * E + n0 + c4] = o;
    }
}

// ---------------------------------------------------------------------------
// Host launcher
// ---------------------------------------------------------------------------
extern "C" void kernel_launch(void* const* d_in, const int* in_sizes, int n_in,
                              void* d_out, int out_size)
{
    const float* query = (const float*)d_in[0];
    const float* key_  = (const float*)d_in[1];
    const float* value = (const float*)d_in[2];
    const float* Wq = (const float*)d_in[4];
    const float* bq = (const float*)d_in[5];
    const float* Wk = (const float*)d_in[6];
    const float* bk = (const float*)d_in[7];
    const float* Wv = (const float*)d_in[8];
    const float* bv = (const float*)d_in[9];
    const float* Wo = (const float*)d_in[10];
    const float* bo = (const float*)d_in[11];
    float* out = (float*)d_out;

    #define SYM(p, s) void* p; cudaGetSymbolAddress(&p, s)
    SYM(qh, g_qh); SYM(ql, g_ql); SYM(kh, g_kh); SYM(kl, g_kl); SYM(vh, g_vh); SYM(vl, g_vl);
    SYM(wqh, g_wqh); SYM(wql, g_wql); SYM(wkh, g_wkh); SYM(wkl, g_wkl);
    SYM(wvh, g_wvh); SYM(wvl, g_wvl); SYM(woh, g_woh); SYM(wol, g_wol);
    SYM(Qh, g_Qh); SYM(Ql, g_Ql); SYM(Kh, g_Kh); SYM(Kl, g_Kl);
    SYM(Vth, g_Vth); SYM(Vtl, g_Vtl);
    SYM(Sc, g_Sc); SYM(Ph, g_Ph); SYM(Pl, g_Pl); SYM(AOh, g_AOh); SYM(AOl, g_AOl);
    #undef SYM
    typedef __nv_bfloat16 bf;

    cudaFuncSetAttribute((const void*)proj_qkv,    cudaFuncAttributeMaxDynamicSharedMemorySize, SMEM_SZ);
    cudaFuncSetAttribute((const void*)scores_mma,  cudaFuncAttributeMaxDynamicSharedMemorySize, SMEM_SZ);
    cudaFuncSetAttribute((const void*)attnv_mma,   cudaFuncAttributeMaxDynamicSharedMemorySize, SMEM_SZ);
    cudaFuncSetAttribute((const void*)outproj_mma, cudaFuncAttributeMaxDynamicSharedMemorySize, SMEM_SZ);

    // 1) fp32 -> bf16 hi/lo conversions (batched)
    const int nIn = M_ROWS * E, nW = E * E;
    cvt3<<<dim3(nIn / 2048, 3), 256>>>(query, key_, value,
        (bf*)qh, (bf*)ql, (bf*)kh, (bf*)kl, (bf*)vh, (bf*)vl);
    cvt4<<<dim3(nW / 2048, 4), 256>>>(Wq, Wk, Wv, Wo,
        (bf*)wqh, (bf*)wql, (bf*)wkh, (bf*)wkl, (bf*)wvh, (bf*)wvl, (bf*)woh, (bf*)wol);

    // 2) fused Q/K/V projections (Q scaled by 1/32, V transposed)
    proj_qkv<<<dim3(E / TN, M_ROWS / TM, 3), NTHR, SMEM_SZ>>>(
        (bf*)qh, (bf*)ql, (bf*)kh, (bf*)kl, (bf*)vh, (bf*)vl,
        (bf*)wqh, (bf*)wql, (bf*)wkh, (bf*)wkl, (bf*)wvh, (bf*)wvl,
        bq, bk, bv,
        (bf*)Qh, (bf*)Ql, (bf*)Kh, (bf*)Kl, (bf*)Vth, (bf*)Vtl);

    // 3) scores — compact triangular grid: 136 tiles per batch, no no-ops
    scores_mma<<<dim3(136, 1, B), NTHR, SMEM_SZ>>>(
        (bf*)Qh, (bf*)Ql, (bf*)Kh, (bf*)Kl, (float*)Sc);

    // 4) fused softmax -> bf16-pair P (longest rows first)
    softmax_pair<<<B * S, 256>>>((const float*)Sc, (bf*)Ph, (bf*)Pl);

    // 5) attn_out = P @ V (longest m-tiles first)
    attnv_mma<<<dim3(E / TN, S / TM, B), NTHR, SMEM_SZ>>>(
        (bf*)Ph, (bf*)Pl, (bf*)Vth, (bf*)Vtl, (bf*)AOh, (bf*)AOl);

    // 6) output projection -> d_out
    outproj_mma<<<dim3(E / TN, M_ROWS / TM, 1), NTHR, SMEM_SZ>>>(
        (bf*)AOh, (bf*)AOl, (bf*)woh, (bf*)wol, bo, out);
}

// round 13
// speedup vs baseline: 1.0837x; 1.0039x over previous
#include <cuda_runtime.h>
#include <cuda_bf16.h>
#include <cstdint>
#include <math.h>

// ---------------------------------------------------------------------------
// Problem constants
// ---------------------------------------------------------------------------
constexpr int B = 4;
constexpr int S = 2048;
constexpr int E = 1024;
constexpr int M_ROWS = B * S;   // 8192

// GEMM tiling: CTA 128x128 (8 warps of 64x32), KB=64 bf16 per chunk
constexpr int TM = 128, TN = 128, KB = 64;
constexpr int NTHR = 256;
constexpr int TILE_BYTES = 128 * 128;          // 16KB per operand tile
constexpr int STAGE_BYTES = 4 * TILE_BYTES;    // Ah, Al, Bh, Bl = 64KB
constexpr int NSTAGE = 3;
constexpr int SMEM_SZ = NSTAGE * STAGE_BYTES;  // 192KB
constexpr int EPIT = 132;                      // fp32 epilogue pitch (words)

// ---------------------------------------------------------------------------
// Scratch (device globals — no allocations allowed)
// ---------------------------------------------------------------------------
__device__ __nv_bfloat16 g_qh[(size_t)M_ROWS * E], g_ql[(size_t)M_ROWS * E];
__device__ __nv_bfloat16 g_kh[(size_t)M_ROWS * E], g_kl[(size_t)M_ROWS * E];
__device__ __nv_bfloat16 g_vh[(size_t)M_ROWS * E], g_vl[(size_t)M_ROWS * E];
__device__ __nv_bfloat16 g_wqh[(size_t)E * E], g_wql[(size_t)E * E];
__device__ __nv_bfloat16 g_wkh[(size_t)E * E], g_wkl[(size_t)E * E];
__device__ __nv_bfloat16 g_wvh[(size_t)E * E], g_wvl[(size_t)E * E];
__device__ __nv_bfloat16 g_woh[(size_t)E * E], g_wol[(size_t)E * E];
__device__ __nv_bfloat16 g_Qh[(size_t)M_ROWS * E], g_Ql[(size_t)M_ROWS * E];
__device__ __nv_bfloat16 g_Kh[(size_t)M_ROWS * E], g_Kl[(size_t)M_ROWS * E];
__device__ __nv_bfloat16 g_Vth[(size_t)B * E * S], g_Vtl[(size_t)B * E * S];
__device__ float         g_Sc[(size_t)B * S * S];
__device__ __nv_bfloat16 g_Ph[(size_t)B * S * S], g_Pl[(size_t)B * S * S];
__device__ __nv_bfloat16 g_AOh[(size_t)M_ROWS * E], g_AOl[(size_t)M_ROWS * E];

// ---------------------------------------------------------------------------
// PTX helpers (Ampere-compatible only: cp.async, ldmatrix, mma.sync)
// ---------------------------------------------------------------------------
__device__ __forceinline__ uint32_t smem_u32(const void* p) {
    uint32_t a;
    asm("{ .reg .u64 t; cvta.to.shared.u64 t, %1; cvt.u32.u64 %0, t; }" : "=r"(a) : "l"(p));
    return a;
}
#define SWZ(o) ((uint32_t)(o) ^ ((((uint32_t)(o)) >> 3) & 0x70))

#define CP_ASYNC16(dst, src) \
    asm volatile("cp.async.cg.shared.global [%0], [%1], 16;" :: "r"(dst), "l"(src) : "memory")
#define CP_COMMIT() asm volatile("cp.async.commit_group;" ::: "memory")
#define CP_WAIT0()  asm volatile("cp.async.wait_group 0;" ::: "memory")
#define CP_WAIT1()  asm volatile("cp.async.wait_group 1;" ::: "memory")

#define LDSM4(r0, r1, r2, r3, a) \
    asm volatile("ldmatrix.sync.aligned.m8n8.x4.shared.b16 {%0,%1,%2,%3}, [%4];" \
                 : "=r"(r0), "=r"(r1), "=r"(r2), "=r"(r3) : "r"(a))

#define MMA16816(c, a, b0, b1) \
    asm volatile("mma.sync.aligned.m16n8k16.row.col.f32.bf16.bf16.f32 " \
                 "{%0,%1,%2,%3},{%4,%5,%6,%7},{%8,%9},{%0,%1,%2,%3};" \
                 : "+f"((c)[0]), "+f"((c)[1]), "+f"((c)[2]), "+f"((c)[3]) \
                 : "r"((a)[0]), "r"((a)[1]), "r"((a)[2]), "r"((a)[3]), \
                   "r"(b0), "r"(b1))

// ---------------------------------------------------------------------------
// Batched fp32 -> (bf16 hi, bf16 lo) conversions (blockIdx.y selects tensor)
// ---------------------------------------------------------------------------
__device__ __forceinline__ void cvt_body(const float* __restrict__ in,
                                         __nv_bfloat16* __restrict__ h,
                                         __nv_bfloat16* __restrict__ l)
{
    int i = (blockIdx.x * 256 + threadIdx.x) * 8;
    float4 a = *(const float4*)(in + i);
    float4 b2 = *(const float4*)(in + i + 4);
    float v[8] = {a.x, a.y, a.z, a.w, b2.x, b2.y, b2.z, b2.w};
    unsigned short hb[8], lb[8];
    #pragma unroll
    for (int j = 0; j < 8; j++) {
        __nv_bfloat16 hv = __float2bfloat16(v[j]);
        float lo = v[j] - __bfloat162float(hv);
        __nv_bfloat16 lv = __float2bfloat16(lo);
        hb[j] = *(unsigned short*)&hv;
        lb[j] = *(unsigned short*)&lv;
    }
    *(uint4*)(h + i) = *(uint4*)hb;
    *(uint4*)(l + i) = *(uint4*)lb;
}

__global__ __launch_bounds__(256) void cvt3(
    const float* __restrict__ i0, const float* __restrict__ i1, const float* __restrict__ i2,
    __nv_bfloat16* h0, __nv_bfloat16* l0, __nv_bfloat16* h1, __nv_bfloat16* l1,
    __nv_bfloat16* h2, __nv_bfloat16* l2)
{
    const int z = blockIdx.y;
    const float* in = (z == 0) ? i0 : (z == 1) ? i1 : i2;
    __nv_bfloat16* h = (z == 0) ? h0 : (z == 1) ? h1 : h2;
    __nv_bfloat16* l = (z == 0) ? l0 : (z == 1) ? l1 : l2;
    cvt_body(in, h, l);
}

__global__ __launch_bounds__(256) void cvt4(
    const float* __restrict__ i0, const float* __restrict__ i1,
    const float* __restrict__ i2, const float* __restrict__ i3,
    __nv_bfloat16* h0, __nv_bfloat16* l0, __nv_bfloat16* h1, __nv_bfloat16* l1,
    __nv_bfloat16* h2, __nv_bfloat16* l2, __nv_bfloat16* h3, __nv_bfloat16* l3)
{
    const int z = blockIdx.y;
    const float* in = (z == 0) ? i0 : (z == 1) ? i1 : (z == 2) ? i2 : i3;
    __nv_bfloat16* h = (z == 0) ? h0 : (z == 1) ? h1 : (z == 2) ? h2 : h3;
    __nv_bfloat16* l = (z == 0) ? l0 : (z == 1) ? l1 : (z == 2) ? l2 : l3;
    cvt_body(in, h, l);
}

// ---------------------------------------------------------------------------
// Fused causal softmax: fp32 scores -> bf16-pair probabilities (zeros padded
// to the 128-multiple so attn@V can run dense up to the diagonal tile).
// Longest rows launched first.
// ---------------------------------------------------------------------------
__global__ __launch_bounds__(256) void softmax_pair(const float* __restrict__ Sc,
                                                    __nv_bfloat16* __restrict__ Ph,
                                                    __nv_bfloat16* __restrict__ Pl)
{
    const int row = blockIdx.x;
    const int b = row >> 11;
    const int q = (S - 1) - (row & (S - 1));   // descending: long rows first
    const float* ptr = Sc + (size_t)b * S * S + (size_t)q * S;
    const int len = q + 1;
    const int plen = ((q >> 7) + 1) << 7;
    const int tid = threadIdx.x;

    float vals[8];
    float m = -INFINITY;
    #pragma unroll
    for (int i = 0; i < 8; i++) {
        int k = tid + i * 256;
        vals[i] = (k < len) ? ptr[k] : -INFINITY;
        m = fmaxf(m, vals[i]);
    }
    __shared__ float red[256];
    red[tid] = m;
    __syncthreads();
    for (int s = 128; s > 0; s >>= 1) {
        if (tid < s) red[tid] = fmaxf(red[tid], red[tid + s]);
        __syncthreads();
    }
    m = red[0];
    __syncthreads();
    float sum = 0.f;
    #pragma unroll
    for (int i = 0; i < 8; i++) {
        int k = tid + i * 256;
        vals[i] = (k < len) ? __expf(vals[i] - m) : 0.f;
        sum += vals[i];
    }
    red[tid] = sum;
    __syncthreads();
    for (int s = 128; s > 0; s >>= 1) {
        if (tid < s) red[tid] += red[tid + s];
        __syncthreads();
    }
    const float inv = 1.0f / red[0];

    __nv_bfloat16* ph = Ph + (size_t)b * S * S + (size_t)q * S;
    __nv_bfloat16* pl = Pl + (size_t)b * S * S + (size_t)q * S;
    #pragma unroll
    for (int i = 0; i < 8; i++) {
        int k = tid + i * 256;
        if (k < plen) {
            float p = vals[i] * inv;
            __nv_bfloat16 h = __float2bfloat16(p);
            ph[k] = h;
            pl[k] = __float2bfloat16(p - __bfloat162float(h));
        }
    }
}

// ---------------------------------------------------------------------------
// GEMM core: 128x128 fp32 tile of A[M,K]*Bop[N,K]^T (split-bf16, 3 terms),
// result in smem ep[128][EPIT].
// 8 warps of 64x32, m16n8k16 via ldmatrix, 3-stage cp.async pipeline.
// Intra-chunk fragment double-buffering: LDSM for k-step ks+1 issue BEFORE
// the MMA block of ks, so smem reads (MIO pipe) overlap tensor-pipe work.
// ---------------------------------------------------------------------------
__device__ __forceinline__ void gemm_core(
    const __nv_bfloat16* __restrict__ Ah, const __nv_bfloat16* __restrict__ Al,
    const __nv_bfloat16* __restrict__ Bh, const __nv_bfloat16* __restrict__ Bl,
    int m0, int n0, int lda, int ldb, int NC, char* smem)
{
    const uint32_t smb = smem_u32(smem);
    const int tid = threadIdx.x;
    const int wid = tid >> 5, lane = tid & 31;
    const int warp_m = wid >> 2;        // 0..1 -> 64-row half
    const int warp_n = wid & 3;         // 0..3 -> 32-col quarter

    auto load_chunk = [&](int c, int s) {
        const int k0 = c * KB;
        const uint32_t stage = smb + s * STAGE_BYTES;
        const __nv_bfloat16* gp[4] = {Ah, Al, Bh, Bl};
        #pragma unroll
        for (int t = 0; t < 4; t++) {
            const __nv_bfloat16* g = gp[t];
            const int r0 = (t < 2) ? m0 : n0;
            const int ld = (t < 2) ? lda : ldb;
            const uint32_t tbase = stage + t * TILE_BYTES;
            #pragma unroll
            for (int i = 0; i < 4; i++) {
                int sg = tid + 256 * i;
                int r = sg >> 3, sc = sg & 7;
                CP_ASYNC16(tbase + SWZ(r * 128 + sc * 16),
                           g + (size_t)(r0 + r) * ld + k0 + sc * 8);
            }
        }
        CP_COMMIT();
    };

    float acc[4][4][4] = {};

    load_chunk(0, 0);
    if (NC > 1) load_chunk(1, 1);

    const int lg = lane >> 3, lr = lane & 7;
    const int rowA = warp_m * 64 + lr + (lg & 1) * 8;
    const int kA   = (lg >> 1) * 16;
    const int rowB = warp_n * 32 + lr + (lg >> 1) * 8;
    const int kBo  = (lg & 1) * 16;

    // double-buffered fragments
    uint32_t ah[2][4][4], al[2][4][4], bh[2][2][4], bl[2][2][4];

    for (int c = 0; c < NC; c++) {
        if (c == NC - 1) { CP_WAIT0(); } else { CP_WAIT1(); }
        __syncthreads();
        if (c + 2 < NC) load_chunk(c + 2, (c + 2) % NSTAGE);

        const uint32_t stage = smb + (c % NSTAGE) * STAGE_BYTES;
        const uint32_t aH = stage, aL = stage + TILE_BYTES;
        const uint32_t bH = stage + 2 * TILE_BYTES, bL = stage + 3 * TILE_BYTES;

        // fragment loader for one k16-step into buffer 'bu'
        auto load_frags = [&](int ks, int bu) {
            const int koA = ks * 32 + kA;
            const int koB = ks * 32 + kBo;
            #pragma unroll
            for (int i = 0; i < 4; i++) {
                uint32_t off = SWZ((rowA + i * 16) * 128 + koA);
                LDSM4(ah[bu][i][0], ah[bu][i][1], ah[bu][i][2], ah[bu][i][3], aH + off);
                LDSM4(al[bu][i][0], al[bu][i][1], al[bu][i][2], al[bu][i][3], aL + off);
            }
            #pragma unroll
            for (int p = 0; p < 2; p++) {
                uint32_t off = SWZ((rowB + p * 16) * 128 + koB);
                LDSM4(bh[bu][p][0], bh[bu][p][1], bh[bu][p][2], bh[bu][p][3], bH + off);
                LDSM4(bl[bu][p][0], bl[bu][p][1], bl[bu][p][2], bl[bu][p][3], bL + off);
            }
        };

        load_frags(0, 0);
        #pragma unroll
        for (int ks = 0; ks < 4; ks++) {
            const int cur = ks & 1, nxt = cur ^ 1;
            if (ks < 3) load_frags(ks + 1, nxt);   // MIO work ahead of tensor work
            #pragma unroll
            for (int i = 0; i < 4; i++)
                #pragma unroll
                for (int j = 0; j < 4; j++) {
                    const int p = j >> 1, h = (j & 1) * 2;
                    MMA16816(acc[i][j], ah[cur][i], bh[cur][p][h], bh[cur][p][h + 1]);
                }
            #pragma unroll
            for (int i = 0; i < 4; i++)
                #pragma unroll
                for (int j = 0; j < 4; j++) {
                    const int p = j >> 1, h = (j & 1) * 2;
                    MMA16816(acc[i][j], al[cur][i], bh[cur][p][h], bh[cur][p][h + 1]);
                }
            #pragma unroll
            for (int i = 0; i < 4; i++)
                #pragma unroll
                for (int j = 0; j < 4; j++) {
                    const int p = j >> 1, h = (j & 1) * 2;
                    MMA16816(acc[i][j], ah[cur][i], bl[cur][p][h], bl[cur][p][h + 1]);
                }
        }
        // no trailing sync: next iteration's leading sync provides the barrier
    }
    __syncthreads();   // all warps done computing before ep overwrites stages

    // regs -> smem ep
    float* ep = (float*)smem;
    const int erow = lane >> 2;
    const int ecol = (lane & 3) * 2;
    #pragma unroll
    for (int i = 0; i < 4; i++) {
        int rbase = warp_m * 64 + i * 16 + erow;
        #pragma unroll
        for (int j = 0; j < 4; j++) {
            int cc = warp_n * 32 + j * 8 + ecol;
            ep[rbase * EPIT + cc]           = acc[i][j][0];
            ep[rbase * EPIT + cc + 1]       = acc[i][j][1];
            ep[(rbase + 8) * EPIT + cc]     = acc[i][j][2];
            ep[(rbase + 8) * EPIT + cc + 1] = acc[i][j][3];
        }
    }
    __syncthreads();
}

// bf16-pair store helper: ep[128][EPIT] (+bias)*scale -> row-major pair arrays
__device__ __forceinline__ void store_pair(
    const float* ep, const float* bias, float scale,
    __nv_bfloat16* oH, __nv_bfloat16* oL, int m0, int n0, int ldc)
{
    const int tid = threadIdx.x;
    #pragma unroll
    for (int i = 0; i < 8; i++) {
        int idx = tid + NTHR * i;
        int r = idx >> 4, c8 = (idx & 15) * 8;
        unsigned short hb[8], lb[8];
        #pragma unroll
        for (int j = 0; j < 8; j++) {
            float v = ep[r * EPIT + c8 + j];
            if (bias) v = (v + bias[n0 + c8 + j]) * scale;
            __nv_bfloat16 hv = __float2bfloat16(v);
            float lo = v - __bfloat162float(hv);
            __nv_bfloat16 lv = __float2bfloat16(lo);
            hb[j] = *(unsigned short*)&hv;
            lb[j] = *(unsigned short*)&lv;
        }
        size_t off = (size_t)(m0 + r) * ldc + n0 + c8;
        *(uint4*)(oH + off) = *(uint4*)hb;
        *(uint4*)(oL + off) = *(uint4*)lb;
    }
}

// ---------------------------------------------------------------------------
// Fused Q/K/V projection: blockIdx.z selects tensor. Q folds the 1/32 scale;
// V writes directly in transposed [b][e][s] bf16-pair layout.
// ---------------------------------------------------------------------------
__global__ __launch_bounds__(NTHR, 1) void proj_qkv(
    const __nv_bfloat16* __restrict__ qh, const __nv_bfloat16* __restrict__ ql,
    const __nv_bfloat16* __restrict__ kh, const __nv_bfloat16* __restrict__ kl,
    const __nv_bfloat16* __restrict__ vh, const __nv_bfloat16* __restrict__ vl,
    const __nv_bfloat16* __restrict__ wqh, const __nv_bfloat16* __restrict__ wql,
    const __nv_bfloat16* __restrict__ wkh, const __nv_bfloat16* __restrict__ wkl,
    const __nv_bfloat16* __restrict__ wvh, const __nv_bfloat16* __restrict__ wvl,
    const float* __restrict__ bq, const float* __restrict__ bk, const float* __restrict__ bv,
    __nv_bfloat16* Qh, __nv_bfloat16* Ql, __nv_bfloat16* Kh, __nv_bfloat16* Kl,
    __nv_bfloat16* Vth, __nv_bfloat16* Vtl)
{
    extern __shared__ __align__(1024) char smem[];
    const int z = blockIdx.z;
    const int m0 = blockIdx.y * TM, n0 = blockIdx.x * TN;

    const __nv_bfloat16 *Ah, *Al, *Bh, *Bl;
    const float* bias;
    if (z == 0)      { Ah = qh; Al = ql; Bh = wqh; Bl = wql; bias = bq; }
    else if (z == 1) { Ah = kh; Al = kl; Bh = wkh; Bl = wkl; bias = bk; }
    else             { Ah = vh; Al = vl; Bh = wvh; Bl = wvl; bias = bv; }

    gemm_core(Ah, Al, Bh, Bl, m0, n0, E, E, E / KB, smem);
    const float* ep = (const float*)smem;
    const int tid = threadIdx.x;

    if (z == 0) {
        store_pair(ep, bias, 0.03125f, Qh, Ql, m0, n0, E);
    } else if (z == 1) {
        store_pair(ep, bias, 1.0f, Kh, Kl, m0, n0, E);
    } else {
        // transposed store: V[m0+r][n0+col] -> Vt[b][n0+col][s0+r]
        const int bb = m0 >> 11;
        const int s0 = m0 & (S - 1);
        const int col = tid & 127, half = tid >> 7;   // rows 0-63 / 64-127
        const float bcol = bias[n0 + col];
        __nv_bfloat16* oH = Vth + ((size_t)bb * E + n0 + col) * S + s0 + half * 64;
        __nv_bfloat16* oL = Vtl + ((size_t)bb * E + n0 + col) * S + s0 + half * 64;
        #pragma unroll
        for (int r0 = 0; r0 < 64; r0 += 8) {
            unsigned short hb[8], lb[8];
            #pragma unroll
            for (int k = 0; k < 8; k++) {
                float v = ep[(half * 64 + r0 + k) * EPIT + col] + bcol;
                __nv_bfloat16 hv = __float2bfloat16(v);
                float lo = v - __bfloat162float(hv);
                __nv_bfloat16 lv = __float2bfloat16(lo);
                hb[k] = *(unsigned short*)&hv;
                lb[k] = *(unsigned short*)&lv;
            }
            *(uint4*)(oH + r0) = *(uint4*)hb;
            *(uint4*)(oL + r0) = *(uint4*)lb;
        }
    }
}

// ---------------------------------------------------------------------------
// Scores: compact triangular grid — blockIdx.x in [0,136) maps to (mi,ni)
// with ni <= mi. No no-op CTAs.
// ---------------------------------------------------------------------------
__global__ __launch_bounds__(NTHR, 1) void scores_mma(
    const __nv_bfloat16* __restrict__ Qh, const __nv_bfloat16* __restrict__ Ql,
    const __nv_bfloat16* __restrict__ Kh, const __nv_bfloat16* __restrict__ Kl,
    float* __restrict__ Sc)
{
    extern __shared__ __align__(1024) char smem[];
    const int b = blockIdx.z;
    const int t = blockIdx.x;
    int mi = (int)((sqrtf(8.0f * (float)t + 1.0f) - 1.0f) * 0.5f);
    while ((mi + 1) * (mi + 2) / 2 <= t) mi++;
    while (mi * (mi + 1) / 2 > t) mi--;
    const int ni = t - mi * (mi + 1) / 2;
    const int m0 = mi * TM, n0 = ni * TN;

    const size_t boff = (size_t)b * S * E;
    gemm_core(Qh + boff, Ql + boff, Kh + boff, Kl + boff, m0, n0, E, E, E / KB, smem);
    const float* ep = (const float*)smem;
    float* oF = Sc + (size_t)b * S * S;
    const int tid = threadIdx.x;
    #pragma unroll
    for (int i = 0; i < 16; i++) {
        int idx = tid + NTHR * i;
        int r = idx >> 5, c4 = (idx & 31) * 4;
        float4 o;
        o.x = ep[r * EPIT + c4 + 0];
        o.y = ep[r * EPIT + c4 + 1];
        o.z = ep[r * EPIT + c4 + 2];
        o.w = ep[r * EPIT + c4 + 3];
        *(float4*)&oF[(size_t)(m0 + r) * S + n0 + c4] = o;
    }
}

// ---------------------------------------------------------------------------
// attn_out = P @ V (K clipped at diagonal tile), bf16-pair out.
// m-tiles remapped descending: longest-running CTAs launch first.
// ---------------------------------------------------------------------------
__global__ __launch_bounds__(NTHR, 1) void attnv_mma(
    const __nv_bfloat16* __restrict__ Ph, const __nv_bfloat16* __restrict__ Pl,
    const __nv_bfloat16* __restrict__ Vth, const __nv_bfloat16* __restrict__ Vtl,
    __nv_bfloat16* AOh, __nv_bfloat16* AOl)
{
    extern __shared__ __align__(1024) char smem[];
    const int b = blockIdx.z;
    const int mi = (gridDim.y - 1) - blockIdx.y;   // longest first
    const int m0 = mi * TM, n0 = blockIdx.x * TN;
    const size_t poff = (size_t)b * S * S, voff = (size_t)b * E * S;

    gemm_core(Ph + poff, Pl + poff, Vth + voff, Vtl + voff,
              m0, n0, S, S, (m0 + TM) / KB, smem);
    const float* ep = (const float*)smem;
    store_pair(ep, nullptr, 1.0f, AOh + (size_t)b * S * E, AOl + (size_t)b * S * E,
               m0, n0, E);
}

// ---------------------------------------------------------------------------
// Output projection: out = AO @ Wo^T + bo (fp32)
// ---------------------------------------------------------------------------
__global__ __launch_bounds__(NTHR, 1) void outproj_mma(
    const __nv_bfloat16* __restrict__ AOh, const __nv_bfloat16* __restrict__ AOl,
    const __nv_bfloat16* __restrict__ woh, const __nv_bfloat16* __restrict__ wol,
    const float* __restrict__ bo, float* __restrict__ out)
{
    extern __shared__ __align__(1024) char smem[];
    const int m0 = blockIdx.y * TM, n0 = blockIdx.x * TN;
    gemm_core(AOh, AOl, woh, wol, m0, n0, E, E, E / KB, smem);
    const float* ep = (const float*)smem;
    const int tid = threadIdx.x;
    #pragma unroll
    for (int i = 0; i < 16; i++) {
        int idx = tid + NTHR * i;
        int r = idx >> 5, c4 = (idx & 31) * 4;
        float4 bv = *(const float4*)&bo[n0 + c4];
        float4 o;
        o.x = ep[r * EPIT + c4 + 0] + bv.x;
        o.y = ep[r * EPIT + c4 + 1] + bv.y;
        o.z = ep[r * EPIT + c4 + 2] + bv.z;
        o.w = ep[r * EPIT + c4 + 3] + bv.w;
        *(float4*)&out[(size_t)(m0 + r) * E + n0 + c4] = o;
    }
}

// ---------------------------------------------------------------------------
// Host launcher
// ---------------------------------------------------------------------------
extern "C" void kernel_launch(void* const* d_in, const int* in_sizes, int n_in,
                              void* d_out, int out_size)
{
    const float* query = (const float*)d_in[0];
    const float* key_  = (const float*)d_in[1];
    const float* value = (const float*)d_in[2];
    const float* Wq = (const float*)d_in[4];
    const float* bq = (const float*)d_in[5];
    const float* Wk = (const float*)d_in[6];
    const float* bk = (const float*)d_in[7];
    const float* Wv = (const float*)d_in[8];
    const float* bv = (const float*)d_in[9];
    const float* Wo = (const float*)d_in[10];
    const float* bo = (const float*)d_in[11];
    float* out = (float*)d_out;

    #define SYM(p, s) void* p; cudaGetSymbolAddress(&p, s)
    SYM(qh, g_qh); SYM(ql, g_ql); SYM(kh, g_kh); SYM(kl, g_kl); SYM(vh, g_vh); SYM(vl, g_vl);
    SYM(wqh, g_wqh); SYM(wql, g_wql); SYM(wkh, g_wkh); SYM(wkl, g_wkl);
    SYM(wvh, g_wvh); SYM(wvl, g_wvl); SYM(woh, g_woh); SYM(wol, g_wol);
    SYM(Qh, g_Qh); SYM(Ql, g_Ql); SYM(Kh, g_Kh); SYM(Kl, g_Kl);
    SYM(Vth, g_Vth); SYM(Vtl, g_Vtl);
    SYM(Sc, g_Sc); SYM(Ph, g_Ph); SYM(Pl, g_Pl); SYM(AOh, g_AOh); SYM(AOl, g_AOl);
    #undef SYM
    typedef __nv_bfloat16 bf;

    cudaFuncSetAttribute((const void*)proj_qkv,    cudaFuncAttributeMaxDynamicSharedMemorySize, SMEM_SZ);
    cudaFuncSetAttribute((const void*)scores_mma,  cudaFuncAttributeMaxDynamicSharedMemorySize, SMEM_SZ);
    cudaFuncSetAttribute((const void*)attnv_mma,   cudaFuncAttributeMaxDynamicSharedMemorySize, SMEM_SZ);
    cudaFuncSetAttribute((const void*)outproj_mma, cudaFuncAttributeMaxDynamicSharedMemorySize, SMEM_SZ);

    // 1) fp32 -> bf16 hi/lo conversions (batched)
    const int nIn = M_ROWS * E, nW = E * E;
    cvt3<<<dim3(nIn / 2048, 3), 256>>>(query, key_, value,
        (bf*)qh, (bf*)ql, (bf*)kh, (bf*)kl, (bf*)vh, (bf*)vl);
    cvt4<<<dim3(nW / 2048, 4), 256>>>(Wq, Wk, Wv, Wo,
        (bf*)wqh, (bf*)wql, (bf*)wkh, (bf*)wkl, (bf*)wvh, (bf*)wvl, (bf*)woh, (bf*)wol);

    // 2) fused Q/K/V projections (Q scaled by 1/32, V transposed)
    proj_qkv<<<dim3(E / TN, M_ROWS / TM, 3), NTHR, SMEM_SZ>>>(
        (bf*)qh, (bf*)ql, (bf*)kh, (bf*)kl, (bf*)vh, (bf*)vl,
        (bf*)wqh, (bf*)wql, (bf*)wkh, (bf*)wkl, (bf*)wvh, (bf*)wvl,
        bq, bk, bv,
        (bf*)Qh, (bf*)Ql, (bf*)Kh, (bf*)Kl, (bf*)Vth, (bf*)Vtl);

    // 3) scores — compact triangular grid: 136 tiles per batch, no no-ops
    scores_mma<<<dim3(136, 1, B), NTHR, SMEM_SZ>>>(
        (bf*)Qh, (bf*)Ql, (bf*)Kh, (bf*)Kl, (float*)Sc);

    // 4) fused softmax -> bf16-pair P (longest rows first)
    softmax_pair<<<B * S, 256>>>((const float*)Sc, (bf*)Ph, (bf*)Pl);

    // 5) attn_out = P @ V (longest m-tiles first)
    attnv_mma<<<dim3(E / TN, S / TM, B), NTHR, SMEM_SZ>>>(
        (bf*)Ph, (bf*)Pl, (bf*)Vth, (bf*)Vtl, (bf*)AOh, (bf*)AOl);

    // 6) output projection -> d_out
    outproj_mma<<<dim3(E / TN, M_ROWS / TM, 1), NTHR, SMEM_SZ>>>(
        (bf*)AOh, (bf*)AOl, (bf*)woh, (bf*)wol, bo, out);
}

// round 14
// speedup vs baseline: 1.5162x; 1.3990x over previous
#include <cuda_runtime.h>
#include <cuda_fp16.h>
#include <cstdint>
#include <math.h>

// ---------------------------------------------------------------------------
// Problem constants
// ---------------------------------------------------------------------------
constexpr int B = 4;
constexpr int S = 2048;
constexpr int E = 1024;
constexpr int M_ROWS = B * S;   // 8192

// GEMM tiling: CTA 128x128 (8 warps of 64x32), KB=64 fp16 per chunk
constexpr int TM = 128, TN = 128, KB = 64;
constexpr int NTHR = 256;
constexpr int TILE_BYTES = 128 * 128;          // 16KB per operand tile (128B rows)
constexpr int STAGE_BYTES = 3 * TILE_BYTES;    // Ah, Al, Bh = 48KB
constexpr int NSTAGE = 3;
constexpr int SMEM_SZ_GEMM = NSTAGE * STAGE_BYTES;      // 144KB
constexpr int EPIT = 132;                      // fp32 epilogue pitch (words)
constexpr int SMEM_SZ = SMEM_SZ_GEMM;          // >= 128*EPIT*4 = 67.6KB

// ---------------------------------------------------------------------------
// Scratch (device globals — no allocations allowed)
// ---------------------------------------------------------------------------
__device__ __half g_qh[(size_t)M_ROWS * E], g_ql[(size_t)M_ROWS * E];
__device__ __half g_kh[(size_t)M_ROWS * E], g_kl[(size_t)M_ROWS * E];
__device__ __half g_vh[(size_t)M_ROWS * E], g_vl[(size_t)M_ROWS * E];
__device__ __half g_wqh[(size_t)E * E];
__device__ __half g_wkh[(size_t)E * E];
__device__ __half g_wvh[(size_t)E * E];
__device__ __half g_woh[(size_t)E * E];
__device__ __half g_Qh[(size_t)M_ROWS * E], g_Ql[(size_t)M_ROWS * E];
__device__ __half g_Kh[(size_t)M_ROWS * E];
__device__ __half g_Vth[(size_t)B * E * S];
__device__ float  g_Sc[(size_t)B * S * S];
__device__ __half g_Ph[(size_t)B * S * S], g_Pl[(size_t)B * S * S];
__device__ __half g_AOh[(size_t)M_ROWS * E], g_AOl[(size_t)M_ROWS * E];

// ---------------------------------------------------------------------------
// PTX helpers (Ampere-compatible only: cp.async, ldmatrix, mma.sync)
// ---------------------------------------------------------------------------
__device__ __forceinline__ uint32_t smem_u32(const void* p) {
    uint32_t a;
    asm("{ .reg .u64 t; cvta.to.shared.u64 t, %1; cvt.u32.u64 %0, t; }" : "=r"(a) : "l"(p));
    return a;
}
#define SWZ(o) ((uint32_t)(o) ^ ((((uint32_t)(o)) >> 3) & 0x70))

#define CP_ASYNC16(dst, src) \
    asm volatile("cp.async.cg.shared.global [%0], [%1], 16;" :: "r"(dst), "l"(src) : "memory")
#define CP_COMMIT() asm volatile("cp.async.commit_group;" ::: "memory")
#define CP_WAIT0()  asm volatile("cp.async.wait_group 0;" ::: "memory")
#define CP_WAIT1()  asm volatile("cp.async.wait_group 1;" ::: "memory")

#define LDSM4(r0, r1, r2, r3, a) \
    asm volatile("ldmatrix.sync.aligned.m8n8.x4.shared.b16 {%0,%1,%2,%3}, [%4];" \
                 : "=r"(r0), "=r"(r1), "=r"(r2), "=r"(r3) : "r"(a))

#define MMAF16(c, a, b0, b1) \
    asm volatile("mma.sync.aligned.m16n8k16.row.col.f32.f16.f16.f32 " \
                 "{%0,%1,%2,%3},{%4,%5,%6,%7},{%8,%9},{%0,%1,%2,%3};" \
                 : "+f"((c)[0]), "+f"((c)[1]), "+f"((c)[2]), "+f"((c)[3]) \
                 : "r"((a)[0]), "r"((a)[1]), "r"((a)[2]), "r"((a)[3]), \
                   "r"(b0), "r"(b1))

// ---------------------------------------------------------------------------
// fp32 -> (fp16 hi, fp16 lo) conversions for the three inputs
// ---------------------------------------------------------------------------
__device__ __forceinline__ void cvt_body(const float* __restrict__ in,
                                         __half* __restrict__ h,
                                         __half* __restrict__ l)
{
    int i = (blockIdx.x * 256 + threadIdx.x) * 8;
    float4 a = *(const float4*)(in + i);
    float4 b2 = *(const float4*)(in + i + 4);
    float v[8] = {a.x, a.y, a.z, a.w, b2.x, b2.y, b2.z, b2.w};
    unsigned short hb[8], lb[8];
    #pragma unroll
    for (int j = 0; j < 8; j++) {
        __half hv = __float2half_rn(v[j]);
        float lo = v[j] - __half2float(hv);
        __half lv = __float2half_rn(lo);
        hb[j] = *(unsigned short*)&hv;
        lb[j] = *(unsigned short*)&lv;
    }
    *(uint4*)(h + i) = *(uint4*)hb;
    *(uint4*)(l + i) = *(uint4*)lb;
}

__global__ __launch_bounds__(256) void cvt3(
    const float* __restrict__ i0, const float* __restrict__ i1, const float* __restrict__ i2,
    __half* h0, __half* l0, __half* h1, __half* l1, __half* h2, __half* l2)
{
    const int z = blockIdx.y;
    const float* in = (z == 0) ? i0 : (z == 1) ? i1 : i2;
    __half* h = (z == 0) ? h0 : (z == 1) ? h1 : h2;
    __half* l = (z == 0) ? l0 : (z == 1) ? l1 : l2;
    cvt_body(in, h, l);
}

// Weights: hi only (B-operands never need a low part in the 2-term scheme)
__global__ __launch_bounds__(256) void cvtw(
    const float* __restrict__ i0, const float* __restrict__ i1,
    const float* __restrict__ i2, const float* __restrict__ i3,
    __half* h0, __half* h1, __half* h2, __half* h3)
{
    const int z = blockIdx.y;
    const float* in = (z == 0) ? i0 : (z == 1) ? i1 : (z == 2) ? i2 : i3;
    __half* h = (z == 0) ? h0 : (z == 1) ? h1 : (z == 2) ? h2 : h3;
    int i = (blockIdx.x * 256 + threadIdx.x) * 8;
    float4 a = *(const float4*)(in + i);
    float4 b2 = *(const float4*)(in + i + 4);
    float v[8] = {a.x, a.y, a.z, a.w, b2.x, b2.y, b2.z, b2.w};
    unsigned short hb[8];
    #pragma unroll
    for (int j = 0; j < 8; j++) {
        __half hv = __float2half_rn(v[j]);
        hb[j] = *(unsigned short*)&hv;
    }
    *(uint4*)(h + i) = *(uint4*)hb;
}

// ---------------------------------------------------------------------------
// Fused causal softmax: fp32 scores -> fp16-pair probabilities (zeros padded
// to the 128-multiple). Longest rows launched first.
// ---------------------------------------------------------------------------
__global__ __launch_bounds__(256) void softmax_pair(const float* __restrict__ Sc,
                                                    __half* __restrict__ Ph,
                                                    __half* __restrict__ Pl)
{
    const int row = blockIdx.x;
    const int b = row >> 11;
    const int q = (S - 1) - (row & (S - 1));   // descending: long rows first
    const float* ptr = Sc + (size_t)b * S * S + (size_t)q * S;
    const int len = q + 1;
    const int plen = ((q >> 7) + 1) << 7;
    const int tid = threadIdx.x;

    float vals[8];
    float m = -INFINITY;
    #pragma unroll
    for (int i = 0; i < 8; i++) {
        int k = tid + i * 256;
        vals[i] = (k < len) ? ptr[k] : -INFINITY;
        m = fmaxf(m, vals[i]);
    }
    __shared__ float red[256];
    red[tid] = m;
    __syncthreads();
    for (int s = 128; s > 0; s >>= 1) {
        if (tid < s) red[tid] = fmaxf(red[tid], red[tid + s]);
        __syncthreads();
    }
    m = red[0];
    __syncthreads();
    float sum = 0.f;
    #pragma unroll
    for (int i = 0; i < 8; i++) {
        int k = tid + i * 256;
        vals[i] = (k < len) ? __expf(vals[i] - m) : 0.f;
        sum += vals[i];
    }
    red[tid] = sum;
    __syncthreads();
    for (int s = 128; s > 0; s >>= 1) {
        if (tid < s) red[tid] += red[tid + s];
        __syncthreads();
    }
    const float inv = 1.0f / red[0];

    __half* ph = Ph + (size_t)b * S * S + (size_t)q * S;
    __half* pl = Pl + (size_t)b * S * S + (size_t)q * S;
    #pragma unroll
    for (int i = 0; i < 8; i++) {
        int k = tid + i * 256;
        if (k < plen) {
            float p = vals[i] * inv;
            __half h = __float2half_rn(p);
            ph[k] = h;
            pl[k] = __float2half_rn(p - __half2float(h));
        }
    }
}

// ---------------------------------------------------------------------------
// GEMM core: 128x128 fp32 tile of A[M,K]*Bop[N,K]^T, 2-term fp16 split:
//   C = Ah*Bh + Al*Bh  (A = hi+lo fp16, B = hi only)
// result in smem ep[128][EPIT].
// 8 warps of 64x32, m16n8k16 via ldmatrix, 3-stage cp.async pipeline,
// intra-chunk fragment double-buffering.
// ---------------------------------------------------------------------------
__device__ __forceinline__ void gemm_core(
    const __half* __restrict__ Ah, const __half* __restrict__ Al,
    const __half* __restrict__ Bh,
    int m0, int n0, int lda, int ldb, int NC, char* smem)
{
    const uint32_t smb = smem_u32(smem);
    const int tid = threadIdx.x;
    const int wid = tid >> 5, lane = tid & 31;
    const int warp_m = wid >> 2;        // 0..1 -> 64-row half
    const int warp_n = wid & 3;         // 0..3 -> 32-col quarter

    auto load_chunk = [&](int c, int s) {
        const int k0 = c * KB;
        const uint32_t stage = smb + s * STAGE_BYTES;
        const __half* gp[3] = {Ah, Al, Bh};
        #pragma unroll
        for (int t = 0; t < 3; t++) {
            const __half* g = gp[t];
            const int r0 = (t < 2) ? m0 : n0;
            const int ld = (t < 2) ? lda : ldb;
            const uint32_t tbase = stage + t * TILE_BYTES;
            #pragma unroll
            for (int i = 0; i < 4; i++) {
                int sg = tid + 256 * i;
                int r = sg >> 3, sc = sg & 7;
                CP_ASYNC16(tbase + SWZ(r * 128 + sc * 16),
                           g + (size_t)(r0 + r) * ld + k0 + sc * 8);
            }
        }
        CP_COMMIT();
    };

    float acc[4][4][4] = {};

    load_chunk(0, 0);
    if (NC > 1) load_chunk(1, 1);

    const int lg = lane >> 3, lr = lane & 7;
    const int rowA = warp_m * 64 + lr + (lg & 1) * 8;
    const int kA   = (lg >> 1) * 16;
    const int rowB = warp_n * 32 + lr + (lg >> 1) * 8;
    const int kBo  = (lg & 1) * 16;

    // double-buffered fragments
    uint32_t ah[2][4][4], al[2][4][4], bh[2][2][4];

    for (int c = 0; c < NC; c++) {
        if (c == NC - 1) { CP_WAIT0(); } else { CP_WAIT1(); }
        __syncthreads();
        if (c + 2 < NC) load_chunk(c + 2, (c + 2) % NSTAGE);

        const uint32_t stage = smb + (c % NSTAGE) * STAGE_BYTES;
        const uint32_t aH = stage, aL = stage + TILE_BYTES;
        const uint32_t bH = stage + 2 * TILE_BYTES;

        auto load_frags = [&](int ks, int bu) {
            const int koA = ks * 32 + kA;
            const int koB = ks * 32 + kBo;
            #pragma unroll
            for (int i = 0; i < 4; i++) {
                uint32_t off = SWZ((rowA + i * 16) * 128 + koA);
                LDSM4(ah[bu][i][0], ah[bu][i][1], ah[bu][i][2], ah[bu][i][3], aH + off);
                LDSM4(al[bu][i][0], al[bu][i][1], al[bu][i][2], al[bu][i][3], aL + off);
            }
            #pragma unroll
            for (int p = 0; p < 2; p++) {
                uint32_t off = SWZ((rowB + p * 16) * 128 + koB);
                LDSM4(bh[bu][p][0], bh[bu][p][1], bh[bu][p][2], bh[bu][p][3], bH + off);
            }
        };

        load_frags(0, 0);
        #pragma unroll
        for (int ks = 0; ks < 4; ks++) {
            const int cur = ks & 1, nxt = cur ^ 1;
            if (ks < 3) load_frags(ks + 1, nxt);
            #pragma unroll
            for (int i = 0; i < 4; i++)
                #pragma unroll
                for (int j = 0; j < 4; j++) {
                    const int p = j >> 1, h = (j & 1) * 2;
                    MMAF16(acc[i][j], ah[cur][i], bh[cur][p][h], bh[cur][p][h + 1]);
                }
            #pragma unroll
            for (int i = 0; i < 4; i++)
                #pragma unroll
                for (int j = 0; j < 4; j++) {
                    const int p = j >> 1, h = (j & 1) * 2;
                    MMAF16(acc[i][j], al[cur][i], bh[cur][p][h], bh[cur][p][h + 1]);
                }
        }
        // no trailing sync: next iteration's leading sync provides the barrier
    }
    __syncthreads();

    // regs -> smem ep
    float* ep = (float*)smem;
    const int erow = lane >> 2;
    const int ecol = (lane & 3) * 2;
    #pragma unroll
    for (int i = 0; i < 4; i++) {
        int rbase = warp_m * 64 + i * 16 + erow;
        #pragma unroll
        for (int j = 0; j < 4; j++) {
            int cc = warp_n * 32 + j * 8 + ecol;
            ep[rbase * EPIT + cc]           = acc[i][j][0];
            ep[rbase * EPIT + cc + 1]       = acc[i][j][1];
            ep[(rbase + 8) * EPIT + cc]     = acc[i][j][2];
            ep[(rbase + 8) * EPIT + cc + 1] = acc[i][j][3];
        }
    }
    __syncthreads();
}

// fp16-pair store: ep[128][EPIT] (+bias)*scale -> hi/lo arrays
__device__ __forceinline__ void store_pair(
    const float* ep, const float* bias, float scale,
    __half* oH, __half* oL, int m0, int n0, int ldc)
{
    const int tid = threadIdx.x;
    #pragma unroll
    for (int i = 0; i < 8; i++) {
        int idx = tid + NTHR * i;
        int r = idx >> 4, c8 = (idx & 15) * 8;
        unsigned short hb[8], lb[8];
        #pragma unroll
        for (int j = 0; j < 8; j++) {
            float v = ep[r * EPIT + c8 + j];
            if (bias) v = (v + bias[n0 + c8 + j]) * scale;
            __half hv = __float2half_rn(v);
            float lo = v - __half2float(hv);
            __half lv = __float2half_rn(lo);
            hb[j] = *(unsigned short*)&hv;
            lb[j] = *(unsigned short*)&lv;
        }
        size_t off = (size_t)(m0 + r) * ldc + n0 + c8;
        *(uint4*)(oH + off) = *(uint4*)hb;
        *(uint4*)(oL + off) = *(uint4*)lb;
    }
}

// fp16 hi-only store: ep[128][EPIT] + bias -> single array
__device__ __forceinline__ void store_hi(
    const float* ep, const float* bias,
    __half* oH, int m0, int n0, int ldc)
{
    const int tid = threadIdx.x;
    #pragma unroll
    for (int i = 0; i < 8; i++) {
        int idx = tid + NTHR * i;
        int r = idx >> 4, c8 = (idx & 15) * 8;
        unsigned short hb[8];
        #pragma unroll
        for (int j = 0; j < 8; j++) {
            float v = ep[r * EPIT + c8 + j] + bias[n0 + c8 + j];
            __half hv = __float2half_rn(v);
            hb[j] = *(unsigned short*)&hv;
        }
        *(uint4*)(oH + (size_t)(m0 + r) * ldc + n0 + c8) = *(uint4*)hb;
    }
}

// ---------------------------------------------------------------------------
// Fused Q/K/V projection: blockIdx.z selects tensor. Q folds the 1/32 scale
// (hi/lo out); K hi-only; V transposed hi-only [b][e][s].
// ---------------------------------------------------------------------------
__global__ __launch_bounds__(NTHR, 1) void proj_qkv(
    const __half* __restrict__ qh, const __half* __restrict__ ql,
    const __half* __restrict__ kh, const __half* __restrict__ kl,
    const __half* __restrict__ vh, const __half* __restrict__ vl,
    const __half* __restrict__ wqh, const __half* __restrict__ wkh,
    const __half* __restrict__ wvh,
    const float* __restrict__ bq, const float* __restrict__ bk, const float* __restrict__ bv,
    __half* Qh, __half* Ql, __half* Kh, __half* Vth)
{
    extern __shared__ __align__(1024) char smem[];
    const int z = blockIdx.z;
    const int m0 = blockIdx.y * TM, n0 = blockIdx.x * TN;

    const __half *Ah, *Al, *Bh;
    const float* bias;
    if (z == 0)      { Ah = qh; Al = ql; Bh = wqh; bias = bq; }
    else if (z == 1) { Ah = kh; Al = kl; Bh = wkh; bias = bk; }
    else             { Ah = vh; Al = vl; Bh = wvh; bias = bv; }

    gemm_core(Ah, Al, Bh, m0, n0, E, E, E / KB, smem);
    const float* ep = (const float*)smem;
    const int tid = threadIdx.x;

    if (z == 0) {
        store_pair(ep, bias, 0.03125f, Qh, Ql, m0, n0, E);
    } else if (z == 1) {
        store_hi(ep, bias, Kh, m0, n0, E);
    } else {
        // transposed hi-only store: V[m0+r][n0+col] -> Vt[b][n0+col][s0+r]
        const int bb = m0 >> 11;
        const int s0 = m0 & (S - 1);
        const int col = tid & 127, half_sel = tid >> 7;   // rows 0-63 / 64-127
        const float bcol = bias[n0 + col];
        __half* oH = Vth + ((size_t)bb * E + n0 + col) * S + s0 + half_sel * 64;
        #pragma unroll
        for (int r0 = 0; r0 < 64; r0 += 8) {
            unsigned short hb[8];
            #pragma unroll
            for (int k = 0; k < 8; k++) {
                float v = ep[(half_sel * 64 + r0 + k) * EPIT + col] + bcol;
                __half hv = __float2half_rn(v);
                hb[k] = *(unsigned short*)&hv;
            }
            *(uint4*)(oH + r0) = *(uint4*)hb;
        }
    }
}

// ---------------------------------------------------------------------------
// Scores: compact triangular grid — no no-op CTAs. fp32 out.
// ---------------------------------------------------------------------------
__global__ __launch_bounds__(NTHR, 1) void scores_mma(
    const __half* __restrict__ Qh, const __half* __restrict__ Ql,
    const __half* __restrict__ Kh, float* __restrict__ Sc)
{
    extern __shared__ __align__(1024) char smem[];
    const int b = blockIdx.z;
    const int t = blockIdx.x;
    int mi = (int)((sqrtf(8.0f * (float)t + 1.0f) - 1.0f) * 0.5f);
    while ((mi + 1) * (mi + 2) / 2 <= t) mi++;
    while (mi * (mi + 1) / 2 > t) mi--;
    const int ni = t - mi * (mi + 1) / 2;
    const int m0 = mi * TM, n0 = ni * TN;

    const size_t boff = (size_t)b * S * E;
    gemm_core(Qh + boff, Ql + boff, Kh + boff, m0, n0, E, E, E / KB, smem);
    const float* ep = (const float*)smem;
    float* oF = Sc + (size_t)b * S * S;
    const int tid = threadIdx.x;
    #pragma unroll
    for (int i = 0; i < 16; i++) {
        int idx = tid + NTHR * i;
        int r = idx >> 5, c4 = (idx & 31) * 4;
        float4 o;
        o.x = ep[r * EPIT + c4 + 0];
        o.y = ep[r * EPIT + c4 + 1];
        o.z = ep[r * EPIT + c4 + 2];
        o.w = ep[r * EPIT + c4 + 3];
        *(float4*)&oF[(size_t)(m0 + r) * S + n0 + c4] = o;
    }
}

// ---------------------------------------------------------------------------
// attn_out = P @ V (K clipped at diagonal tile), fp16-pair out.
// Longest m-tiles first.
// ---------------------------------------------------------------------------
__global__ __launch_bounds__(NTHR, 1) void attnv_mma(
    const __half* __restrict__ Ph, const __half* __restrict__ Pl,
    const __half* __restrict__ Vth,
    __half* AOh, __half* AOl)
{
    extern __shared__ __align__(1024) char smem[];
    const int b = blockIdx.z;
    const int mi = (gridDim.y - 1) - blockIdx.y;   // longest first
    const int m0 = mi * TM, n0 = blockIdx.x * TN;
    const size_t poff = (size_t)b * S * S, voff = (size_t)b * E * S;

    gemm_core(Ph + poff, Pl + poff, Vth + voff,
              m0, n0, S, S, (m0 + TM) / KB, smem);
    const float* ep = (const float*)smem;
    store_pair(ep, nullptr, 1.0f, AOh + (size_t)b * S * E, AOl + (size_t)b * S * E,
               m0, n0, E);
}

// ---------------------------------------------------------------------------
// Output projection: out = AO @ Wo^T + bo (fp32)
// ---------------------------------------------------------------------------
__global__ __launch_bounds__(NTHR, 1) void outproj_mma(
    const __half* __restrict__ AOh, const __half* __restrict__ AOl,
    const __half* __restrict__ woh,
    const float* __restrict__ bo, float* __restrict__ out)
{
    extern __shared__ __align__(1024) char smem[];
    const int m0 = blockIdx.y * TM, n0 = blockIdx.x * TN;
    gemm_core(AOh, AOl, woh, m0, n0, E, E, E / KB, smem);
    const float* ep = (const float*)smem;
    const int tid = threadIdx.x;
    #pragma unroll
    for (int i = 0; i < 16; i++) {
        int idx = tid + NTHR * i;
        int r = idx >> 5, c4 = (idx & 31) * 4;
        float4 bv = *(const float4*)&bo[n0 + c4];
        float4 o;
        o.x = ep[r * EPIT + c4 + 0] + bv.x;
        o.y = ep[r * EPIT + c4 + 1] + bv.y;
        o.z = ep[r * EPIT + c4 + 2] + bv.z;
        o.w = ep[r * EPIT + c4 + 3] + bv.w;
        *(float4*)&out[(size_t)(m0 + r) * E + n0 + c4] = o;
    }
}

// ---------------------------------------------------------------------------
// Host launcher
// ---------------------------------------------------------------------------
extern "C" void kernel_launch(void* const* d_in, const int* in_sizes, int n_in,
                              void* d_out, int out_size)
{
    const float* query = (const float*)d_in[0];
    const float* key_  = (const float*)d_in[1];
    const float* value = (const float*)d_in[2];
    const float* Wq = (const float*)d_in[4];
    const float* bq = (const float*)d_in[5];
    const float* Wk = (const float*)d_in[6];
    const float* bk = (const float*)d_in[7];
    const float* Wv = (const float*)d_in[8];
    const float* bv = (const float*)d_in[9];
    const float* Wo = (const float*)d_in[10];
    const float* bo = (const float*)d_in[11];
    float* out = (float*)d_out;

    #define SYM(p, s) void* p; cudaGetSymbolAddress(&p, s)
    SYM(qh, g_qh); SYM(ql, g_ql); SYM(kh, g_kh); SYM(kl, g_kl); SYM(vh, g_vh); SYM(vl, g_vl);
    SYM(wqh, g_wqh); SYM(wkh, g_wkh); SYM(wvh, g_wvh); SYM(woh, g_woh);
    SYM(Qh, g_Qh); SYM(Ql, g_Ql); SYM(Kh, g_Kh); SYM(Vth, g_Vth);
    SYM(Sc, g_Sc); SYM(Ph, g_Ph); SYM(Pl, g_Pl); SYM(AOh, g_AOh); SYM(AOl, g_AOl);
    #undef SYM
    typedef __half hf;

    cudaFuncSetAttribute((const void*)proj_qkv,    cudaFuncAttributeMaxDynamicSharedMemorySize, SMEM_SZ);
    cudaFuncSetAttribute((const void*)scores_mma,  cudaFuncAttributeMaxDynamicSharedMemorySize, SMEM_SZ);
    cudaFuncSetAttribute((const void*)attnv_mma,   cudaFuncAttributeMaxDynamicSharedMemorySize, SMEM_SZ);
    cudaFuncSetAttribute((const void*)outproj_mma, cudaFuncAttributeMaxDynamicSharedMemorySize, SMEM_SZ);

    // 1) fp32 -> fp16 conversions (inputs hi/lo; weights hi-only)
    const int nIn = M_ROWS * E, nW = E * E;
    cvt3<<<dim3(nIn / 2048, 3), 256>>>(query, key_, value,
        (hf*)qh, (hf*)ql, (hf*)kh, (hf*)kl, (hf*)vh, (hf*)vl);
    cvtw<<<dim3(nW / 2048, 4), 256>>>(Wq, Wk, Wv, Wo,
        (hf*)wqh, (hf*)wkh, (hf*)wvh, (hf*)woh);

    // 2) fused Q/K/V projections (Q scaled by 1/32 hi/lo; K hi; V transposed hi)
    proj_qkv<<<dim3(E / TN, M_ROWS / TM, 3), NTHR, SMEM_SZ>>>(
        (hf*)qh, (hf*)ql, (hf*)kh, (hf*)kl, (hf*)vh, (hf*)vl,
        (hf*)wqh, (hf*)wkh, (hf*)wvh,
        bq, bk, bv,
        (hf*)Qh, (hf*)Ql, (hf*)Kh, (hf*)Vth);

    // 3) scores — compact triangular grid
    scores_mma<<<dim3(136, 1, B), NTHR, SMEM_SZ>>>(
        (hf*)Qh, (hf*)Ql, (hf*)Kh, (float*)Sc);

    // 4) fused softmax -> fp16-pair P (longest rows first)
    softmax_pair<<<B * S, 256>>>((const float*)Sc, (hf*)Ph, (hf*)Pl);

    // 5) attn_out = P @ V (longest m-tiles first)
    attnv_mma<<<dim3(E / TN, S / TM, B), NTHR, SMEM_SZ>>>(
        (hf*)Ph, (hf*)Pl, (hf*)Vth, (hf*)AOh, (hf*)AOl);

    // 6) output projection -> d_out
    outproj_mma<<<dim3(E / TN, M_ROWS / TM, 1), NTHR, SMEM_SZ>>>(
        (hf*)AOh, (hf*)AOl, (hf*)woh, bo, out);
}